// round 15
// baseline (speedup 1.0000x reference)
#include <cuda_runtime.h>
#include <cuda_bf16.h>
#include <stdint.h>
#include <math.h>

#define BB 8
#define SS 512
#define DD 768
#define HH 12
#define DKK 64
#define FF 3072
#define LL 12
#define MTOK (BB*SS)
#define NHB (BB*HH)
#define SCALE 0.125f
#define NQKV 2304

typedef __nv_bfloat16 bf16;

// ------------------------------- scratch -----------------------------------
__device__ __align__(256) float g_x[MTOK*DD];
__device__ __align__(256) float g_t[MTOK*DD];
__device__ __align__(256) bf16 g_xh[MTOK*DD], g_xl[MTOK*DD];
__device__ __align__(256) bf16 g_ah[MTOK*DD], g_al[MTOK*DD];
__device__ __align__(256) bf16 g_qh[MTOK*DD], g_ql[MTOK*DD];
__device__ __align__(256) bf16 g_kh[MTOK*DD], g_kl[MTOK*DD];
__device__ __align__(256) bf16 g_vth[MTOK*DD], g_vtl[MTOK*DD];   // V^T [b,h,dk,s]
__device__ __align__(256) bf16 g_ch[MTOK*DD], g_cl[MTOK*DD];
__device__ __align__(256) bf16 g_hh[MTOK*FF], g_hl[MTOK*FF];
__device__ __align__(256) bf16 g_wqkvh[(long)LL*NQKV*DD], g_wqkvl[(long)LL*NQKV*DD];
__device__ __align__(256) bf16 g_woh[LL*DD*DD], g_wol[LL*DD*DD];
__device__ __align__(256) bf16 g_w1h[(long)LL*FF*DD], g_w1l[(long)LL*FF*DD];
__device__ __align__(256) bf16 g_w2h[(long)LL*DD*FF], g_w2l[(long)LL*DD*FF];

// ----------------------------- helpers --------------------------------------
__device__ __forceinline__ uint32_t smem_u32(const void* p) {
    uint32_t a;
    asm("{ .reg .u64 t; cvta.to.shared.u64 t, %1; cvt.u32.u64 %0, t; }"
        : "=r"(a) : "l"(p));
    return a;
}
__device__ __forceinline__ void cpasync16(uint32_t saddr, const void* gaddr) {
    asm volatile("cp.async.ca.shared.global [%0], [%1], 16;"
                 :: "r"(saddr), "l"(gaddr) : "memory");
}
__device__ __forceinline__ void ldmx4(uint32_t* r, uint32_t addr) {
    asm volatile("ldmatrix.sync.aligned.m8n8.x4.shared.b16 {%0,%1,%2,%3}, [%4];"
                 : "=r"(r[0]), "=r"(r[1]), "=r"(r[2]), "=r"(r[3]) : "r"(addr));
}
__device__ __forceinline__ void mma16816(float* c, const uint32_t* a,
                                         uint32_t b0, uint32_t b1) {
    asm volatile(
        "mma.sync.aligned.m16n8k16.row.col.f32.bf16.bf16.f32 "
        "{%0,%1,%2,%3}, {%4,%5,%6,%7}, {%8,%9}, {%0,%1,%2,%3};"
        : "+f"(c[0]), "+f"(c[1]), "+f"(c[2]), "+f"(c[3])
        : "r"(a[0]), "r"(a[1]), "r"(a[2]), "r"(a[3]), "r"(b0), "r"(b1));
}
__device__ __forceinline__ void store_hl4(bf16* __restrict__ H, bf16* __restrict__ L,
                                          long dst, const float* v) {
    union { bf16 b[4]; uint2 u; } uh, ul;
    #pragma unroll
    for (int i = 0; i < 4; i++) {
        bf16 h = __float2bfloat16_rn(v[i]);
        uh.b[i] = h;
        ul.b[i] = __float2bfloat16_rn(v[i] - __bfloat162float(h));
    }
    *(uint2*)(H + dst) = uh.u;
    *(uint2*)(L + dst) = ul.u;
}
__device__ __forceinline__ uint32_t packbf2(float a, float b) {
    __nv_bfloat162 t = __floats2bfloat162_rn(a, b);
    return *(uint32_t*)&t;
}

// ------------------------- mm_kernel (128x128, 4 warps) ----------------------
#define MATB 10240
#define STGB (4*MATB)
#define MMSMEM 81920

extern __shared__ __align__(16) char smem_[];

__global__ void __launch_bounds__(128, 2) mm_kernel(
    const bf16* __restrict__ Ah, const bf16* __restrict__ Al, long sA,
    const bf16* __restrict__ Bh, const bf16* __restrict__ Bl, long sB,
    const float* __restrict__ bias, const float* __restrict__ bias2,
    const float* __restrict__ bias3, float alpha, int M, int N, int K,
    float* __restrict__ outF, bf16* __restrict__ o1H, bf16* __restrict__ o1L,
    bf16* __restrict__ o2H, bf16* __restrict__ o2L,
    bf16* __restrict__ o3H, bf16* __restrict__ o3L, long sC, int mode)
{
    uint32_t su = smem_u32(smem_);
    int tid = threadIdx.x, wid = tid >> 5, lane = tid & 31;
    int wm = wid & 1, wn = wid >> 1;
    int z = blockIdx.z;
    Ah += (long)z * sA;  Al += (long)z * sA;
    Bh += (long)z * sB;  Bl += (long)z * sB;
    int m0 = blockIdx.y * 128, n0 = blockIdx.x * 128;

    const int C = K >> 5;
    float acc[4][8][4];
    #pragma unroll
    for (int i = 0; i < 4; i++)
        #pragma unroll
        for (int j = 0; j < 8; j++)
            #pragma unroll
            for (int q = 0; q < 4; q++) acc[i][j][q] = 0.f;

    auto loadst = [&](int c, int s) {
        int k0 = c << 5;
        uint32_t sbase = su + s * STGB;
        #pragma unroll
        for (int i = 0; i < 4; i++) {
            int ch = tid + i * 128;
            int row = ch >> 2, c16 = ch & 3;
            uint32_t so = sbase + row * 80 + c16 * 16;
            long ka = (long)(m0 + row) * K + k0 + c16 * 8;
            long kb = (long)(n0 + row) * K + k0 + c16 * 8;
            cpasync16(so,            Ah + ka);
            cpasync16(so + MATB,     Al + ka);
            cpasync16(so + 2 * MATB, Bh + kb);
            cpasync16(so + 3 * MATB, Bl + kb);
        }
        asm volatile("cp.async.commit_group;" ::: "memory");
    };

    auto compute = [&](int s) {
        uint32_t tb = su + s * STGB;
        #pragma unroll
        for (int kk = 0; kk < 2; kk++) {
            int kb = kk * 32;
            uint32_t ah[4][4], al[4][4];
            #pragma unroll
            for (int mt = 0; mt < 4; mt++) {
                uint32_t ad = tb + (wm * 64 + mt * 16 + (lane & 15)) * 80
                              + kb + ((lane >> 4) * 16);
                ldmx4(ah[mt], ad);
                ldmx4(al[mt], ad + MATB);
            }
            uint32_t bh[2][4], bl[2][4];
            uint32_t bbase = tb + 2 * MATB
                           + (wn * 64 + (lane >> 4) * 8 + (lane & 7)) * 80
                           + kb + (((lane >> 3) & 1) * 16);
            ldmx4(bh[0], bbase);
            ldmx4(bl[0], bbase + MATB);
            #pragma unroll
            for (int p = 0; p < 4; p++) {
                int cur = p & 1;
                if (p < 3) {
                    uint32_t bd = bbase + (p + 1) * 16 * 80;
                    ldmx4(bh[cur ^ 1], bd);
                    ldmx4(bl[cur ^ 1], bd + MATB);
                }
                #pragma unroll
                for (int half = 0; half < 2; half++)
                    #pragma unroll
                    for (int mt = 0; mt < 4; mt++)
                        mma16816(acc[mt][p * 2 + half], ah[mt],
                                 bh[cur][half * 2], bh[cur][half * 2 + 1]);
                #pragma unroll
                for (int half = 0; half < 2; half++)
                    #pragma unroll
                    for (int mt = 0; mt < 4; mt++)
                        mma16816(acc[mt][p * 2 + half], ah[mt],
                                 bl[cur][half * 2], bl[cur][half * 2 + 1]);
                #pragma unroll
                for (int half = 0; half < 2; half++)
                    #pragma unroll
                    for (int mt = 0; mt < 4; mt++)
                        mma16816(acc[mt][p * 2 + half], al[mt],
                                 bh[cur][half * 2], bh[cur][half * 2 + 1]);
            }
        }
    };

    loadst(0, 0);
    for (int c = 0; c < C; c++) {
        if (c + 1 < C) {
            loadst(c + 1, (c + 1) & 1);
            asm volatile("cp.async.wait_group 1;" ::: "memory");
        } else {
            asm volatile("cp.async.wait_group 0;" ::: "memory");
        }
        __syncthreads();
        compute(c & 1);
        __syncthreads();
    }

    float* Cs = (float*)smem_;   // [128][132]
    {
        int gr = lane >> 2, gc = (lane & 3) * 2;
        #pragma unroll
        for (int mt = 0; mt < 4; mt++)
            #pragma unroll
            for (int nt = 0; nt < 8; nt++) {
                int row = wm * 64 + mt * 16 + gr;
                int col = wn * 64 + nt * 8 + gc;
                Cs[row * 132 + col]           = acc[mt][nt][0];
                Cs[row * 132 + col + 1]       = acc[mt][nt][1];
                Cs[(row + 8) * 132 + col]     = acc[mt][nt][2];
                Cs[(row + 8) * 132 + col + 1] = acc[mt][nt][3];
            }
    }
    __syncthreads();

    if (mode == 0) {
        for (int idx = tid; idx < 128 * 32; idx += 128) {
            int rr = idx >> 5, c4 = (idx & 31) << 2;
            float4 vv = *(const float4*)(Cs + rr * 132 + c4);
            vv.x *= alpha; vv.y *= alpha; vv.z *= alpha; vv.w *= alpha;
            *(float4*)(outF + (long)z * sC + (long)(m0 + rr) * N + n0 + c4) = vv;
        }
    } else if (mode == 1) {
        for (int idx = tid; idx < 128 * 32; idx += 128) {
            int rr = idx >> 5, c4 = (idx & 31) << 2;
            float4 vv = *(const float4*)(Cs + rr * 132 + c4);
            float v[4] = {vv.x, vv.y, vv.z, vv.w};
            if (bias) {
                float4 bb = *(const float4*)(bias + n0 + c4);
                v[0] += bb.x; v[1] += bb.y; v[2] += bb.z; v[3] += bb.w;
            }
            store_hl4(o1H, o1L, (long)(m0 + rr) * N + n0 + c4, v);
        }
    } else {
        int seg = n0 / DD;            // 0:Q 1:K 2:V
        int nl0 = n0 - seg * DD;
        if (seg < 2) {
            const float* bb = (seg == 0) ? bias : bias2;
            bf16* H = (seg == 0) ? o1H : o2H;
            bf16* L = (seg == 0) ? o1L : o2L;
            for (int idx = tid; idx < 128 * 32; idx += 128) {
                int rr = idx >> 5, c4 = (idx & 31) << 2;
                float4 vv = *(const float4*)(Cs + rr * 132 + c4);
                float4 bbv = *(const float4*)(bb + nl0 + c4);
                float v[4] = {vv.x + bbv.x, vv.y + bbv.y, vv.z + bbv.z, vv.w + bbv.w};
                int mg = m0 + rr, b = mg >> 9, sI = mg & 511;
                int ng = nl0 + c4, hh = ng >> 6, dk = ng & 63;
                long dst = (((long)(b * HH + hh) * SS + sI) << 6) + dk;
                store_hl4(H, L, dst, v);
            }
        } else {
            int b = m0 >> 9, s0v = m0 & 511;
            for (int idx = tid; idx < 128 * 32; idx += 128) {
                int n = idx >> 5, rg = (idx & 31) << 2;
                int ng = nl0 + n, hh = ng >> 6, dk = ng & 63;
                float badd = bias3[ng];
                float v[4];
                #pragma unroll
                for (int i = 0; i < 4; i++) v[i] = Cs[(rg + i) * 132 + n] + badd;
                long dst = (((long)(b * HH + hh) * DKK + dk) << 9) + s0v + rg;
                store_hl4(o3H, o3L, dst, v);
            }
        }
    }
}

// ---------------------- mm64m_kernel (64x128, 4 warps) -----------------------
// Half-height tiles for wave packing. mode 0: fp32; mode 1: hi/lo (+bias).
#define M64A2 5120
#define M64B2 10240
#define STG64M (2*M64A2 + 2*M64B2)   // 30720
#define MM64MSMEM 61440

__global__ void __launch_bounds__(128, 2) mm64m_kernel(
    const bf16* __restrict__ Ah, const bf16* __restrict__ Al,
    const bf16* __restrict__ Bh, const bf16* __restrict__ Bl,
    const float* __restrict__ bias, int M, int N, int K,
    float* __restrict__ outF, bf16* __restrict__ outH, bf16* __restrict__ outL,
    int mode)
{
    uint32_t su = smem_u32(smem_);
    int tid = threadIdx.x, wid = tid >> 5, lane = tid & 31;
    int wm = wid & 1, wn = wid >> 1;
    int m0 = blockIdx.y * 64, n0 = blockIdx.x * 128;

    const int C = K >> 5;
    float acc[2][8][4];
    #pragma unroll
    for (int i = 0; i < 2; i++)
        #pragma unroll
        for (int j = 0; j < 8; j++)
            #pragma unroll
            for (int q = 0; q < 4; q++) acc[i][j][q] = 0.f;

    auto loadst = [&](int c, int s) {
        int k0 = c << 5;
        uint32_t sbase = su + s * STG64M;
        #pragma unroll
        for (int i = 0; i < 2; i++) {
            int ch = tid + i * 128;
            int row = ch >> 2, c16 = ch & 3;
            uint32_t so = sbase + row * 80 + c16 * 16;
            long ka = (long)(m0 + row) * K + k0 + c16 * 8;
            cpasync16(so,          Ah + ka);
            cpasync16(so + M64A2,  Al + ka);
        }
        #pragma unroll
        for (int i = 0; i < 4; i++) {
            int ch = tid + i * 128;
            int row = ch >> 2, c16 = ch & 3;
            uint32_t so = sbase + 2 * M64A2 + row * 80 + c16 * 16;
            long kb = (long)(n0 + row) * K + k0 + c16 * 8;
            cpasync16(so,          Bh + kb);
            cpasync16(so + M64B2,  Bl + kb);
        }
        asm volatile("cp.async.commit_group;" ::: "memory");
    };

    auto compute = [&](int s) {
        uint32_t tb = su + s * STG64M;
        #pragma unroll
        for (int kk = 0; kk < 2; kk++) {
            int kb = kk * 32;
            uint32_t ah[2][4], al[2][4];
            #pragma unroll
            for (int mt = 0; mt < 2; mt++) {
                uint32_t ad = tb + (wm * 32 + mt * 16 + (lane & 15)) * 80
                              + kb + ((lane >> 4) * 16);
                ldmx4(ah[mt], ad);
                ldmx4(al[mt], ad + M64A2);
            }
            uint32_t bh[2][4], bl[2][4];
            uint32_t bbase = tb + 2 * M64A2
                           + (wn * 64 + (lane >> 4) * 8 + (lane & 7)) * 80
                           + kb + (((lane >> 3) & 1) * 16);
            ldmx4(bh[0], bbase);
            ldmx4(bl[0], bbase + M64B2);
            #pragma unroll
            for (int p = 0; p < 4; p++) {
                int cur = p & 1;
                if (p < 3) {
                    uint32_t bd = bbase + (p + 1) * 16 * 80;
                    ldmx4(bh[cur ^ 1], bd);
                    ldmx4(bl[cur ^ 1], bd + M64B2);
                }
                #pragma unroll
                for (int half = 0; half < 2; half++)
                    #pragma unroll
                    for (int mt = 0; mt < 2; mt++)
                        mma16816(acc[mt][p * 2 + half], ah[mt],
                                 bh[cur][half * 2], bh[cur][half * 2 + 1]);
                #pragma unroll
                for (int half = 0; half < 2; half++)
                    #pragma unroll
                    for (int mt = 0; mt < 2; mt++)
                        mma16816(acc[mt][p * 2 + half], ah[mt],
                                 bl[cur][half * 2], bl[cur][half * 2 + 1]);
                #pragma unroll
                for (int half = 0; half < 2; half++)
                    #pragma unroll
                    for (int mt = 0; mt < 2; mt++)
                        mma16816(acc[mt][p * 2 + half], al[mt],
                                 bh[cur][half * 2], bh[cur][half * 2 + 1]);
            }
        }
    };

    loadst(0, 0);
    for (int c = 0; c < C; c++) {
        if (c + 1 < C) {
            loadst(c + 1, (c + 1) & 1);
            asm volatile("cp.async.wait_group 1;" ::: "memory");
        } else {
            asm volatile("cp.async.wait_group 0;" ::: "memory");
        }
        __syncthreads();
        compute(c & 1);
        __syncthreads();
    }

    float* Cs = (float*)smem_;   // [64][132]
    {
        int gr = lane >> 2, gc = (lane & 3) * 2;
        #pragma unroll
        for (int mt = 0; mt < 2; mt++)
            #pragma unroll
            for (int nt = 0; nt < 8; nt++) {
                int row = wm * 32 + mt * 16 + gr;
                int col = wn * 64 + nt * 8 + gc;
                Cs[row * 132 + col]           = acc[mt][nt][0];
                Cs[row * 132 + col + 1]       = acc[mt][nt][1];
                Cs[(row + 8) * 132 + col]     = acc[mt][nt][2];
                Cs[(row + 8) * 132 + col + 1] = acc[mt][nt][3];
            }
    }
    __syncthreads();

    for (int idx = tid; idx < 64 * 32; idx += 128) {
        int rr = idx >> 5, c4 = (idx & 31) << 2;
        float4 vv = *(const float4*)(Cs + rr * 132 + c4);
        if (mode == 0) {
            *(float4*)(outF + (long)(m0 + rr) * N + n0 + c4) = vv;
        } else {
            float v[4] = {vv.x, vv.y, vv.z, vv.w};
            if (bias) {
                float4 bb = *(const float4*)(bias + n0 + c4);
                v[0] += bb.x; v[1] += bb.y; v[2] += bb.z; v[3] += bb.w;
            }
            store_hl4(outH, outL, (long)(m0 + rr) * N + n0 + c4, v);
        }
    }
}

// --------------------------- flash attention ---------------------------------
// Single-stage K/V smem (108.5KB) -> 2 CTAs/SM. Co-resident CTA hides the
// serialized tile load. 8 warps x 16 q-rows, 4 k-tiles of 128 keys.
#define QPITCH 144
#define VPITCH 272
#define QS_OFF 0
#define QSB 18432
#define KS_OFF (2*QSB)            // 36864
#define VS_OFF (KS_OFF + 2*QSB)   // 73728
#define VSB 17408
#define FSMEM (VS_OFF + 2*VSB)    // 108544

__global__ void __launch_bounds__(256, 1) flash_kernel(
    const bf16* __restrict__ qh, const bf16* __restrict__ ql,
    const bf16* __restrict__ kh, const bf16* __restrict__ kl,
    const bf16* __restrict__ vth, const bf16* __restrict__ vtl,
    const float* __restrict__ amask,
    bf16* __restrict__ ch, bf16* __restrict__ cl)
{
    uint32_t su = smem_u32(smem_);
    int tid = threadIdx.x, w = tid >> 5, lane = tid & 31;
    int z = blockIdx.y;
    int b = z / HH, h = z - b * HH;
    int q0 = blockIdx.x * 128;
    const bf16* Qh = qh + (long)z * SS * DKK;
    const bf16* Ql = ql + (long)z * SS * DKK;
    const bf16* Kh = kh + (long)z * SS * DKK;
    const bf16* Kl = kl + (long)z * SS * DKK;
    const bf16* Vh = vth + (long)z * DKK * SS;
    const bf16* Vl = vtl + (long)z * DKK * SS;

    for (int i = tid; i < 1024; i += 256) {
        int r = i >> 3, c = i & 7;
        uint32_t so = su + QS_OFF + r * QPITCH + c * 16;
        long go = (long)(q0 + r) * DKK + c * 8;
        cpasync16(so,        Qh + go);
        cpasync16(so + QSB,  Ql + go);
    }
    auto loadKV = [&](int kt) {
        for (int i = tid; i < 1024; i += 256) {
            int r = i >> 3, c = i & 7;
            uint32_t so = su + KS_OFF + r * QPITCH + c * 16;
            long go = (long)(kt * 128 + r) * DKK + c * 8;
            cpasync16(so,        Kh + go);
            cpasync16(so + QSB,  Kl + go);
        }
        for (int i = tid; i < 1024; i += 256) {
            int r = i >> 4, c = i & 15;
            uint32_t so = su + VS_OFF + r * VPITCH + c * 16;
            long go = (long)r * SS + kt * 128 + c * 8;
            cpasync16(so,        Vh + go);
            cpasync16(so + VSB,  Vl + go);
        }
        asm volatile("cp.async.commit_group;" ::: "memory");
    };

    float acc_o[8][4];
    #pragma unroll
    for (int j = 0; j < 8; j++)
        #pragma unroll
        for (int q = 0; q < 4; q++) acc_o[j][q] = 0.f;
    float rm[2] = {-INFINITY, -INFINITY};
    float rl[2] = {0.f, 0.f};
    int gr = lane >> 2, gc2 = (lane & 3) * 2;

    for (int kt = 0; kt < 4; kt++) {
        loadKV(kt);
        asm volatile("cp.async.wait_group 0;" ::: "memory");
        __syncthreads();

        float accs[16][4];
        #pragma unroll
        for (int j = 0; j < 16; j++)
            #pragma unroll
            for (int q = 0; q < 4; q++) accs[j][q] = 0.f;
        uint32_t kbase = su + KS_OFF;
        #pragma unroll
        for (int kb = 0; kb < 4; kb++) {
            uint32_t aqh[4], aql[4];
            uint32_t ad = su + QS_OFF + (w * 16 + (lane & 15)) * QPITCH
                          + kb * 32 + ((lane >> 4) * 16);
            ldmx4(aqh, ad);
            ldmx4(aql, ad + QSB);
            uint32_t bhf[2][4], blf[2][4];
            uint32_t bd0 = kbase + ((lane >> 4) * 8 + (lane & 7)) * QPITCH
                           + kb * 32 + (((lane >> 3) & 1) * 16);
            ldmx4(bhf[0], bd0);
            ldmx4(blf[0], bd0 + QSB);
            #pragma unroll
            for (int pr = 0; pr < 8; pr++) {
                int cur = pr & 1;
                if (pr < 7) {
                    uint32_t bd = bd0 + (pr + 1) * 16 * QPITCH;
                    ldmx4(bhf[cur ^ 1], bd);
                    ldmx4(blf[cur ^ 1], bd + QSB);
                }
                #pragma unroll
                for (int hf = 0; hf < 2; hf++)
                    mma16816(accs[pr * 2 + hf], aqh, bhf[cur][hf * 2], bhf[cur][hf * 2 + 1]);
                #pragma unroll
                for (int hf = 0; hf < 2; hf++)
                    mma16816(accs[pr * 2 + hf], aqh, blf[cur][hf * 2], blf[cur][hf * 2 + 1]);
                #pragma unroll
                for (int hf = 0; hf < 2; hf++)
                    mma16816(accs[pr * 2 + hf], aql, bhf[cur][hf * 2], bhf[cur][hf * 2 + 1]);
            }
        }

        const float* mrow = amask + b * SS + kt * 128;
        float tmax0 = -INFINITY, tmax1 = -INFINITY;
        #pragma unroll
        for (int nt = 0; nt < 16; nt++) {
            int c0 = nt * 8 + gc2;
            float m0 = mrow[c0], m1 = mrow[c0 + 1];
            float v0 = accs[nt][0] * SCALE, v1 = accs[nt][1] * SCALE;
            float v2 = accs[nt][2] * SCALE, v3 = accs[nt][3] * SCALE;
            if (m0 == 0.f) { v0 = -1e9f; v2 = -1e9f; }
            if (m1 == 0.f) { v1 = -1e9f; v3 = -1e9f; }
            accs[nt][0] = v0; accs[nt][1] = v1; accs[nt][2] = v2; accs[nt][3] = v3;
            tmax0 = fmaxf(tmax0, fmaxf(v0, v1));
            tmax1 = fmaxf(tmax1, fmaxf(v2, v3));
        }
        tmax0 = fmaxf(tmax0, __shfl_xor_sync(0xffffffffu, tmax0, 1));
        tmax0 = fmaxf(tmax0, __shfl_xor_sync(0xffffffffu, tmax0, 2));
        tmax1 = fmaxf(tmax1, __shfl_xor_sync(0xffffffffu, tmax1, 1));
        tmax1 = fmaxf(tmax1, __shfl_xor_sync(0xffffffffu, tmax1, 2));
        float nm0 = fmaxf(rm[0], tmax0), nm1 = fmaxf(rm[1], tmax1);
        float al0 = __expf(rm[0] - nm0), al1 = __expf(rm[1] - nm1);
        rm[0] = nm0; rm[1] = nm1;
        #pragma unroll
        for (int j = 0; j < 8; j++) {
            acc_o[j][0] *= al0; acc_o[j][1] *= al0;
            acc_o[j][2] *= al1; acc_o[j][3] *= al1;
        }
        rl[0] *= al0; rl[1] *= al1;

        uint32_t vbase = su + VS_OFF;
        float rs0 = 0.f, rs1 = 0.f;
        #pragma unroll
        for (int kc = 0; kc < 8; kc++) {
            float p[2][4];
            #pragma unroll
            for (int hf = 0; hf < 2; hf++) {
                int nt = kc * 2 + hf;
                p[hf][0] = __expf(accs[nt][0] - nm0);
                p[hf][1] = __expf(accs[nt][1] - nm0);
                p[hf][2] = __expf(accs[nt][2] - nm1);
                p[hf][3] = __expf(accs[nt][3] - nm1);
                rs0 += p[hf][0] + p[hf][1];
                rs1 += p[hf][2] + p[hf][3];
            }
            uint32_t pah[4], pal[4];
            #pragma unroll
            for (int hf = 0; hf < 2; hf++) {
                float h0 = __bfloat162float(__float2bfloat16_rn(p[hf][0]));
                float h1 = __bfloat162float(__float2bfloat16_rn(p[hf][1]));
                float h2 = __bfloat162float(__float2bfloat16_rn(p[hf][2]));
                float h3 = __bfloat162float(__float2bfloat16_rn(p[hf][3]));
                pah[hf * 2]     = packbf2(h0, h1);
                pah[hf * 2 + 1] = packbf2(h2, h3);
                pal[hf * 2]     = packbf2(p[hf][0] - h0, p[hf][1] - h1);
                pal[hf * 2 + 1] = packbf2(p[hf][2] - h2, p[hf][3] - h3);
            }
            uint32_t vhf[2][4], vlf[2][4];
            uint32_t vd0 = vbase + ((lane >> 4) * 8 + (lane & 7)) * VPITCH
                           + kc * 32 + (((lane >> 3) & 1) * 16);
            ldmx4(vhf[0], vd0);
            ldmx4(vlf[0], vd0 + VSB);
            #pragma unroll
            for (int vp = 0; vp < 4; vp++) {
                int cur = vp & 1;
                if (vp < 3) {
                    uint32_t vd = vd0 + (vp + 1) * 16 * VPITCH;
                    ldmx4(vhf[cur ^ 1], vd);
                    ldmx4(vlf[cur ^ 1], vd + VSB);
                }
                #pragma unroll
                for (int hf = 0; hf < 2; hf++)
                    mma16816(acc_o[vp * 2 + hf], pah, vhf[cur][hf * 2], vhf[cur][hf * 2 + 1]);
                #pragma unroll
                for (int hf = 0; hf < 2; hf++)
                    mma16816(acc_o[vp * 2 + hf], pah, vlf[cur][hf * 2], vlf[cur][hf * 2 + 1]);
                #pragma unroll
                for (int hf = 0; hf < 2; hf++)
                    mma16816(acc_o[vp * 2 + hf], pal, vhf[cur][hf * 2], vhf[cur][hf * 2 + 1]);
            }
        }
        rl[0] += rs0;
        rl[1] += rs1;
        __syncthreads();   // protect K/V smem before next tile's load
    }
    rl[0] += __shfl_xor_sync(0xffffffffu, rl[0], 1);
    rl[0] += __shfl_xor_sync(0xffffffffu, rl[0], 2);
    rl[1] += __shfl_xor_sync(0xffffffffu, rl[1], 1);
    rl[1] += __shfl_xor_sync(0xffffffffu, rl[1], 2);

    float* Cs = (float*)(smem_ + KS_OFF);     // [128][68]
    {
        float inv0 = 1.f / rl[0], inv1 = 1.f / rl[1];
        int r0 = w * 16 + gr;
        #pragma unroll
        for (int no = 0; no < 8; no++) {
            int col = no * 8 + gc2;
            Cs[r0 * 68 + col]           = acc_o[no][0] * inv0;
            Cs[r0 * 68 + col + 1]       = acc_o[no][1] * inv0;
            Cs[(r0 + 8) * 68 + col]     = acc_o[no][2] * inv1;
            Cs[(r0 + 8) * 68 + col + 1] = acc_o[no][3] * inv1;
        }
    }
    __syncthreads();
    for (int idx = tid; idx < 128 * 16; idx += 256) {
        int r = idx >> 4, c4 = (idx & 15) << 2;
        float4 vv = *(const float4*)(Cs + r * 68 + c4);
        float v[4] = {vv.x, vv.y, vv.z, vv.w};
        long dst = ((long)(b * SS + q0 + r)) * DD + h * DKK + c4;
        store_hl4(ch, cl, dst, v);
    }
}

// --------------------------- elementwise kernels -----------------------------
__device__ __forceinline__ float bsum(float v, float* sh) {
    int lane = threadIdx.x & 31, w = threadIdx.x >> 5;
    #pragma unroll
    for (int o = 16; o > 0; o >>= 1) v += __shfl_xor_sync(0xffffffffu, v, o);
    if (lane == 0) sh[w] = v;
    __syncthreads();
    float r = 0.f;
    #pragma unroll
    for (int i = 0; i < 8; i++) r += sh[i];
    __syncthreads();
    return r;
}
__device__ __forceinline__ void wsplit(bf16* H, bf16* L, long i, float v) {
    bf16 h = __float2bfloat16_rn(v);
    H[i] = h;
    L[i] = __float2bfloat16_rn(v - __bfloat162float(h));
}

#define S1 ((long)LL*DD*DD)
#define S2 ((long)LL*FF*DD)
__global__ void cvt_all_kernel(const float* __restrict__ Wq, const float* __restrict__ Wk,
                               const float* __restrict__ Wv, const float* __restrict__ Wo,
                               const float* __restrict__ W1, const float* __restrict__ W2,
                               bf16* __restrict__ qkvh, bf16* __restrict__ qkvl,
                               bf16* __restrict__ woh, bf16* __restrict__ wol,
                               bf16* __restrict__ w1h, bf16* __restrict__ w1l,
                               bf16* __restrict__ w2h, bf16* __restrict__ w2l) {
    const long total = 4 * S1 + 2 * S2;
    long i = (long)blockIdx.x * 256 + threadIdx.x;
    long stride = (long)gridDim.x * 256;
    for (; i < total; i += stride) {
        long j = i;
        if (j < 3 * S1) {
            int seg = (int)(j / S1);
            long r = j - (long)seg * S1;
            const float* src = (seg == 0) ? Wq : (seg == 1) ? Wk : Wv;
            long l = r / (DD * DD);
            long rem = r - l * (DD * DD);
            long n = rem / DD, k = rem - n * DD;
            long dst = (l * NQKV + seg * DD + n) * DD + k;
            wsplit(qkvh, qkvl, dst, src[r]);
        } else if (j < 4 * S1) {
            long r = j - 3 * S1;
            wsplit(woh, wol, r, Wo[r]);
        } else if (j < 4 * S1 + S2) {
            long r = j - 4 * S1;
            wsplit(w1h, w1l, r, W1[r]);
        } else {
            long r = j - 4 * S1 - S2;
            wsplit(w2h, w2l, r, W2[r]);
        }
    }
}

__global__ void embed_ln_kernel(const int* __restrict__ ids, const int* __restrict__ tt,
                                const float* __restrict__ we, const float* __restrict__ pe,
                                const float* __restrict__ te, const float* __restrict__ gamma,
                                const float* __restrict__ beta, float* __restrict__ outF,
                                bf16* __restrict__ outH, bf16* __restrict__ outL) {
    __shared__ float sh[8];
    int m = blockIdx.x, s = m & (SS - 1);
    int id = ids[m], ty = tt[m], t = threadIdx.x;
    float v[3];
    #pragma unroll
    for (int i = 0; i < 3; i++) {
        int d = t + i * 256;
        v[i] = we[(long)id * DD + d] + te[(long)ty * DD + d] + pe[(long)s * DD + d];
    }
    float mu = bsum(v[0] + v[1] + v[2], sh) * (1.f / DD);
    float qs = 0.f;
    #pragma unroll
    for (int i = 0; i < 3; i++) { float d0 = v[i] - mu; qs += d0 * d0; }
    float rstd = rsqrtf(bsum(qs, sh) * (1.f / DD) + 1e-12f);
    #pragma unroll
    for (int i = 0; i < 3; i++) {
        int d = t + i * 256;
        float y = (v[i] - mu) * rstd * gamma[d] + beta[d];
        outF[(long)m * DD + d] = y;
        wsplit(outH, outL, (long)m * DD + d, y);
    }
}

__global__ void ln768_kernel(const float* __restrict__ in, const float* __restrict__ resid,
                             const float* __restrict__ bias, const float* __restrict__ gamma,
                             const float* __restrict__ beta, float* __restrict__ outF,
                             bf16* __restrict__ outH, bf16* __restrict__ outL, float eps) {
    __shared__ float sh[8];
    long m = blockIdx.x;
    int t = threadIdx.x;
    float v[3];
    #pragma unroll
    for (int i = 0; i < 3; i++) {
        int d = t + i * 256;
        float x = in[m * DD + d];
        if (bias) x += bias[d];
        if (resid) x += resid[m * DD + d];
        v[i] = x;
    }
    float mu = bsum(v[0] + v[1] + v[2], sh) * (1.f / DD);
    float qs = 0.f;
    #pragma unroll
    for (int i = 0; i < 3; i++) { float d0 = v[i] - mu; qs += d0 * d0; }
    float rstd = rsqrtf(bsum(qs, sh) * (1.f / DD) + eps);
    #pragma unroll
    for (int i = 0; i < 3; i++) {
        int d = t + i * 256;
        float y = (v[i] - mu) * rstd * gamma[d] + beta[d];
        if (outF) outF[m * DD + d] = y;
        wsplit(outH, outL, m * DD + d, y);
    }
}

// ------------------------------- launch --------------------------------------
extern "C" void kernel_launch(void* const* d_in, const int* in_sizes, int n_in,
                              void* d_out, int out_size) {
    const int*   input_ids = (const int*)  d_in[0];
    const int*   type_ids  = (const int*)  d_in[1];
    const float* amask     = (const float*)d_in[2];
    const float* word_emb  = (const float*)d_in[3];
    const float* pos_emb   = (const float*)d_in[4];
    const float* type_emb  = (const float*)d_in[5];
    const float* emb_g     = (const float*)d_in[6];
    const float* emb_b     = (const float*)d_in[7];
    const float* Wq = (const float*)d_in[8];  const float* bq = (const float*)d_in[9];
    const float* Wk = (const float*)d_in[10]; const float* bk = (const float*)d_in[11];
    const float* Wv = (const float*)d_in[12]; const float* bv = (const float*)d_in[13];
    const float* Wo = (const float*)d_in[14]; const float* bo = (const float*)d_in[15];
    const float* ag = (const float*)d_in[16]; const float* ab = (const float*)d_in[17];
    const float* W1 = (const float*)d_in[18]; const float* b1 = (const float*)d_in[19];
    const float* W2 = (const float*)d_in[20]; const float* b2 = (const float*)d_in[21];
    const float* fg = (const float*)d_in[22]; const float* fb = (const float*)d_in[23];

    static int smem_set = 0;
    if (!smem_set) {
        cudaFuncSetAttribute(mm_kernel, cudaFuncAttributeMaxDynamicSharedMemorySize, MMSMEM);
        cudaFuncSetAttribute(mm64m_kernel, cudaFuncAttributeMaxDynamicSharedMemorySize, MM64MSMEM);
        cudaFuncSetAttribute(flash_kernel, cudaFuncAttributeMaxDynamicSharedMemorySize, FSMEM);
        smem_set = 1;
    }

    float *x, *t;
    bf16 *xh, *xl, *ah, *al, *qh, *ql, *kh, *kl, *vth, *vtl, *ch, *cl, *hh, *hl;
    bf16 *qkvh, *qkvl, *woh, *wol, *w1h, *w1l, *w2h, *w2l;
    cudaGetSymbolAddress((void**)&x, g_x);     cudaGetSymbolAddress((void**)&t, g_t);
    cudaGetSymbolAddress((void**)&xh, g_xh);   cudaGetSymbolAddress((void**)&xl, g_xl);
    cudaGetSymbolAddress((void**)&ah, g_ah);   cudaGetSymbolAddress((void**)&al, g_al);
    cudaGetSymbolAddress((void**)&qh, g_qh);   cudaGetSymbolAddress((void**)&ql, g_ql);
    cudaGetSymbolAddress((void**)&kh, g_kh);   cudaGetSymbolAddress((void**)&kl, g_kl);
    cudaGetSymbolAddress((void**)&vth, g_vth); cudaGetSymbolAddress((void**)&vtl, g_vtl);
    cudaGetSymbolAddress((void**)&ch, g_ch);   cudaGetSymbolAddress((void**)&cl, g_cl);
    cudaGetSymbolAddress((void**)&hh, g_hh);   cudaGetSymbolAddress((void**)&hl, g_hl);
    cudaGetSymbolAddress((void**)&qkvh, g_wqkvh); cudaGetSymbolAddress((void**)&qkvl, g_wqkvl);
    cudaGetSymbolAddress((void**)&woh, g_woh); cudaGetSymbolAddress((void**)&wol, g_wol);
    cudaGetSymbolAddress((void**)&w1h, g_w1h); cudaGetSymbolAddress((void**)&w1l, g_w1l);
    cudaGetSymbolAddress((void**)&w2h, g_w2h); cudaGetSymbolAddress((void**)&w2l, g_w2l);

    cvt_all_kernel<<<8192, 256>>>(Wq, Wk, Wv, Wo, W1, W2,
                                  qkvh, qkvl, woh, wol, w1h, w1l, w2h, w2l);

    embed_ln_kernel<<<MTOK, 256>>>(input_ids, type_ids, word_emb, pos_emb,
                                   type_emb, emb_g, emb_b, x, xh, xl);

    for (int l = 0; l < LL; l++) {
        const bf16* qkh = qkvh + (long)l * NQKV * DD;
        const bf16* qkl = qkvl + (long)l * NQKV * DD;
        // fused QKV (576 CTAs, packs well)
        mm_kernel<<<dim3(18, 32), 128, MMSMEM>>>(xh, xl, 0, qkh, qkl, 0,
            bq + l * DD, bk + l * DD, bv + l * DD, 1.f, MTOK, NQKV, DD,
            nullptr, qh, ql, kh, kl, vth, vtl, 0, 5);
        // fused attention (2 CTAs/SM)
        flash_kernel<<<dim3(4, NHB), 256, FSMEM>>>(qh, ql, kh, kl, vth, vtl,
                                                   amask, ch, cl);
        // O projection -> fp32 t (BM=64)
        mm64m_kernel<<<dim3(6, 64), 128, MM64MSMEM>>>(ch, cl,
            woh + (long)l * DD * DD, wol + (long)l * DD * DD, nullptr,
            MTOK, DD, DD, t, nullptr, nullptr, 0);
        ln768_kernel<<<MTOK, 256>>>(t, x, bo + l * DD, ag + l * DD, ab + l * DD,
                                    nullptr, ah, al, 1e-5f);
        // FFN1 -> hi/lo h (+bias) (BM=64: 1536 CTAs)
        mm64m_kernel<<<dim3(24, 64), 128, MM64MSMEM>>>(ah, al,
            w1h + (long)l * FF * DD, w1l + (long)l * FF * DD, b1 + l * FF,
            MTOK, FF, DD, nullptr, hh, hl, 1);
        // FFN2 -> fp32 t (BM=64)
        mm64m_kernel<<<dim3(6, 64), 128, MM64MSMEM>>>(hh, hl,
            w2h + (long)l * DD * FF, w2l + (long)l * DD * FF, nullptr,
            MTOK, DD, FF, t, nullptr, nullptr, 0);
        ln768_kernel<<<MTOK, 256>>>(t, nullptr, b2 + l * DD, fg + l * DD,
                                    fb + l * DD, x, xh, xl, 1e-5f);
    }

    cudaMemcpyAsync(d_out, x, (size_t)MTOK * DD * sizeof(float),
                    cudaMemcpyDeviceToDevice);
}

// round 16
// speedup vs baseline: 1.7492x; 1.7492x over previous
#include <cuda_runtime.h>
#include <cuda_bf16.h>
#include <stdint.h>
#include <math.h>

#define BB 8
#define SS 512
#define DD 768
#define HH 12
#define DKK 64
#define FF 3072
#define LL 12
#define MTOK (BB*SS)
#define NHB (BB*HH)
#define SCALE 0.125f
#define NQKV 2304

typedef __nv_bfloat16 bf16;

// ------------------------------- scratch -----------------------------------
__device__ __align__(256) float g_x[MTOK*DD];
__device__ __align__(256) float g_t[MTOK*DD];
__device__ __align__(256) bf16 g_xh[MTOK*DD], g_xl[MTOK*DD];
__device__ __align__(256) bf16 g_ah[MTOK*DD], g_al[MTOK*DD];
__device__ __align__(256) bf16 g_qh[MTOK*DD], g_ql[MTOK*DD];
__device__ __align__(256) bf16 g_kh[MTOK*DD], g_kl[MTOK*DD];
__device__ __align__(256) bf16 g_vth[MTOK*DD], g_vtl[MTOK*DD];   // V^T [b,h,dk,s]
__device__ __align__(256) bf16 g_ch[MTOK*DD], g_cl[MTOK*DD];
__device__ __align__(256) bf16 g_wqkvh[(long)LL*NQKV*DD], g_wqkvl[(long)LL*NQKV*DD];
__device__ __align__(256) bf16 g_woh[LL*DD*DD], g_wol[LL*DD*DD];
__device__ __align__(256) bf16 g_w1th[(long)LL*DD*FF], g_w1tl[(long)LL*DD*FF]; // W1^T [l][e][f]
__device__ __align__(256) bf16 g_w2h[(long)LL*DD*FF], g_w2l[(long)LL*DD*FF];   // W2 [l][d][f]
__device__ __align__(256) bf16 g_weffh[LL*DD*DD], g_weffl[LL*DD*DD];           // W2@W1 [l][d][e]
__device__ __align__(256) float g_beff[LL*DD];

// ----------------------------- helpers --------------------------------------
__device__ __forceinline__ uint32_t smem_u32(const void* p) {
    uint32_t a;
    asm("{ .reg .u64 t; cvta.to.shared.u64 t, %1; cvt.u32.u64 %0, t; }"
        : "=r"(a) : "l"(p));
    return a;
}
__device__ __forceinline__ void cpasync16(uint32_t saddr, const void* gaddr) {
    asm volatile("cp.async.ca.shared.global [%0], [%1], 16;"
                 :: "r"(saddr), "l"(gaddr) : "memory");
}
__device__ __forceinline__ void ldmx4(uint32_t* r, uint32_t addr) {
    asm volatile("ldmatrix.sync.aligned.m8n8.x4.shared.b16 {%0,%1,%2,%3}, [%4];"
                 : "=r"(r[0]), "=r"(r[1]), "=r"(r[2]), "=r"(r[3]) : "r"(addr));
}
__device__ __forceinline__ void mma16816(float* c, const uint32_t* a,
                                         uint32_t b0, uint32_t b1) {
    asm volatile(
        "mma.sync.aligned.m16n8k16.row.col.f32.bf16.bf16.f32 "
        "{%0,%1,%2,%3}, {%4,%5,%6,%7}, {%8,%9}, {%0,%1,%2,%3};"
        : "+f"(c[0]), "+f"(c[1]), "+f"(c[2]), "+f"(c[3])
        : "r"(a[0]), "r"(a[1]), "r"(a[2]), "r"(a[3]), "r"(b0), "r"(b1));
}
__device__ __forceinline__ void store_hl4(bf16* __restrict__ H, bf16* __restrict__ L,
                                          long dst, const float* v) {
    union { bf16 b[4]; uint2 u; } uh, ul;
    #pragma unroll
    for (int i = 0; i < 4; i++) {
        bf16 h = __float2bfloat16_rn(v[i]);
        uh.b[i] = h;
        ul.b[i] = __float2bfloat16_rn(v[i] - __bfloat162float(h));
    }
    *(uint2*)(H + dst) = uh.u;
    *(uint2*)(L + dst) = ul.u;
}
__device__ __forceinline__ uint32_t packbf2(float a, float b) {
    __nv_bfloat162 t = __floats2bfloat162_rn(a, b);
    return *(uint32_t*)&t;
}

// ------------------------- mm_kernel (128x128, 4 warps) ----------------------
#define MATB 10240
#define STGB (4*MATB)
#define MMSMEM 81920

extern __shared__ __align__(16) char smem_[];

__global__ void __launch_bounds__(128, 2) mm_kernel(
    const bf16* __restrict__ Ah, const bf16* __restrict__ Al, long sA,
    const bf16* __restrict__ Bh, const bf16* __restrict__ Bl, long sB,
    const float* __restrict__ bias, const float* __restrict__ bias2,
    const float* __restrict__ bias3, float alpha, int M, int N, int K,
    float* __restrict__ outF, bf16* __restrict__ o1H, bf16* __restrict__ o1L,
    bf16* __restrict__ o2H, bf16* __restrict__ o2L,
    bf16* __restrict__ o3H, bf16* __restrict__ o3L, long sC, int mode)
{
    uint32_t su = smem_u32(smem_);
    int tid = threadIdx.x, wid = tid >> 5, lane = tid & 31;
    int wm = wid & 1, wn = wid >> 1;
    int z = blockIdx.z;
    Ah += (long)z * sA;  Al += (long)z * sA;
    Bh += (long)z * sB;  Bl += (long)z * sB;
    int m0 = blockIdx.y * 128, n0 = blockIdx.x * 128;

    const int C = K >> 5;
    float acc[4][8][4];
    #pragma unroll
    for (int i = 0; i < 4; i++)
        #pragma unroll
        for (int j = 0; j < 8; j++)
            #pragma unroll
            for (int q = 0; q < 4; q++) acc[i][j][q] = 0.f;

    auto loadst = [&](int c, int s) {
        int k0 = c << 5;
        uint32_t sbase = su + s * STGB;
        #pragma unroll
        for (int i = 0; i < 4; i++) {
            int ch = tid + i * 128;
            int row = ch >> 2, c16 = ch & 3;
            uint32_t so = sbase + row * 80 + c16 * 16;
            long ka = (long)(m0 + row) * K + k0 + c16 * 8;
            long kb = (long)(n0 + row) * K + k0 + c16 * 8;
            cpasync16(so,            Ah + ka);
            cpasync16(so + MATB,     Al + ka);
            cpasync16(so + 2 * MATB, Bh + kb);
            cpasync16(so + 3 * MATB, Bl + kb);
        }
        asm volatile("cp.async.commit_group;" ::: "memory");
    };

    auto compute = [&](int s) {
        uint32_t tb = su + s * STGB;
        #pragma unroll
        for (int kk = 0; kk < 2; kk++) {
            int kb = kk * 32;
            uint32_t ah[4][4], al[4][4];
            #pragma unroll
            for (int mt = 0; mt < 4; mt++) {
                uint32_t ad = tb + (wm * 64 + mt * 16 + (lane & 15)) * 80
                              + kb + ((lane >> 4) * 16);
                ldmx4(ah[mt], ad);
                ldmx4(al[mt], ad + MATB);
            }
            uint32_t bh[2][4], bl[2][4];
            uint32_t bbase = tb + 2 * MATB
                           + (wn * 64 + (lane >> 4) * 8 + (lane & 7)) * 80
                           + kb + (((lane >> 3) & 1) * 16);
            ldmx4(bh[0], bbase);
            ldmx4(bl[0], bbase + MATB);
            #pragma unroll
            for (int p = 0; p < 4; p++) {
                int cur = p & 1;
                if (p < 3) {
                    uint32_t bd = bbase + (p + 1) * 16 * 80;
                    ldmx4(bh[cur ^ 1], bd);
                    ldmx4(bl[cur ^ 1], bd + MATB);
                }
                #pragma unroll
                for (int half = 0; half < 2; half++)
                    #pragma unroll
                    for (int mt = 0; mt < 4; mt++)
                        mma16816(acc[mt][p * 2 + half], ah[mt],
                                 bh[cur][half * 2], bh[cur][half * 2 + 1]);
                #pragma unroll
                for (int half = 0; half < 2; half++)
                    #pragma unroll
                    for (int mt = 0; mt < 4; mt++)
                        mma16816(acc[mt][p * 2 + half], ah[mt],
                                 bl[cur][half * 2], bl[cur][half * 2 + 1]);
                #pragma unroll
                for (int half = 0; half < 2; half++)
                    #pragma unroll
                    for (int mt = 0; mt < 4; mt++)
                        mma16816(acc[mt][p * 2 + half], al[mt],
                                 bh[cur][half * 2], bh[cur][half * 2 + 1]);
            }
        }
    };

    loadst(0, 0);
    for (int c = 0; c < C; c++) {
        if (c + 1 < C) {
            loadst(c + 1, (c + 1) & 1);
            asm volatile("cp.async.wait_group 1;" ::: "memory");
        } else {
            asm volatile("cp.async.wait_group 0;" ::: "memory");
        }
        __syncthreads();
        compute(c & 1);
        __syncthreads();
    }

    float* Cs = (float*)smem_;   // [128][132]
    {
        int gr = lane >> 2, gc = (lane & 3) * 2;
        #pragma unroll
        for (int mt = 0; mt < 4; mt++)
            #pragma unroll
            for (int nt = 0; nt < 8; nt++) {
                int row = wm * 64 + mt * 16 + gr;
                int col = wn * 64 + nt * 8 + gc;
                Cs[row * 132 + col]           = acc[mt][nt][0];
                Cs[row * 132 + col + 1]       = acc[mt][nt][1];
                Cs[(row + 8) * 132 + col]     = acc[mt][nt][2];
                Cs[(row + 8) * 132 + col + 1] = acc[mt][nt][3];
            }
    }
    __syncthreads();

    if (mode == 0) {
        for (int idx = tid; idx < 128 * 32; idx += 128) {
            int rr = idx >> 5, c4 = (idx & 31) << 2;
            float4 vv = *(const float4*)(Cs + rr * 132 + c4);
            vv.x *= alpha; vv.y *= alpha; vv.z *= alpha; vv.w *= alpha;
            *(float4*)(outF + (long)z * sC + (long)(m0 + rr) * N + n0 + c4) = vv;
        }
    } else if (mode == 1) {
        for (int idx = tid; idx < 128 * 32; idx += 128) {
            int rr = idx >> 5, c4 = (idx & 31) << 2;
            float4 vv = *(const float4*)(Cs + rr * 132 + c4);
            float v[4] = {vv.x, vv.y, vv.z, vv.w};
            if (bias) {
                float4 bb = *(const float4*)(bias + n0 + c4);
                v[0] += bb.x; v[1] += bb.y; v[2] += bb.z; v[3] += bb.w;
            }
            store_hl4(o1H, o1L, (long)z * sC + (long)(m0 + rr) * N + n0 + c4, v);
        }
    } else {
        int seg = n0 / DD;            // 0:Q 1:K 2:V
        int nl0 = n0 - seg * DD;
        if (seg < 2) {
            const float* bb = (seg == 0) ? bias : bias2;
            bf16* H = (seg == 0) ? o1H : o2H;
            bf16* L = (seg == 0) ? o1L : o2L;
            for (int idx = tid; idx < 128 * 32; idx += 128) {
                int rr = idx >> 5, c4 = (idx & 31) << 2;
                float4 vv = *(const float4*)(Cs + rr * 132 + c4);
                float4 bbv = *(const float4*)(bb + nl0 + c4);
                float v[4] = {vv.x + bbv.x, vv.y + bbv.y, vv.z + bbv.z, vv.w + bbv.w};
                int mg = m0 + rr, b = mg >> 9, sI = mg & 511;
                int ng = nl0 + c4, hh = ng >> 6, dk = ng & 63;
                long dst = (((long)(b * HH + hh) * SS + sI) << 6) + dk;
                store_hl4(H, L, dst, v);
            }
        } else {
            int b = m0 >> 9, s0v = m0 & 511;
            for (int idx = tid; idx < 128 * 32; idx += 128) {
                int n = idx >> 5, rg = (idx & 31) << 2;
                int ng = nl0 + n, hh = ng >> 6, dk = ng & 63;
                float badd = bias3[ng];
                float v[4];
                #pragma unroll
                for (int i = 0; i < 4; i++) v[i] = Cs[(rg + i) * 132 + n] + badd;
                long dst = (((long)(b * HH + hh) * DKK + dk) << 9) + s0v + rg;
                store_hl4(o3H, o3L, dst, v);
            }
        }
    }
}

// ---------------------- mm64m_kernel (64x128, 4 warps) -----------------------
#define M64A2 5120
#define M64B2 10240
#define STG64M (2*M64A2 + 2*M64B2)
#define MM64MSMEM 61440

__global__ void __launch_bounds__(128, 2) mm64m_kernel(
    const bf16* __restrict__ Ah, const bf16* __restrict__ Al,
    const bf16* __restrict__ Bh, const bf16* __restrict__ Bl,
    const float* __restrict__ bias, int M, int N, int K,
    float* __restrict__ outF, bf16* __restrict__ outH, bf16* __restrict__ outL,
    int mode)
{
    uint32_t su = smem_u32(smem_);
    int tid = threadIdx.x, wid = tid >> 5, lane = tid & 31;
    int wm = wid & 1, wn = wid >> 1;
    int m0 = blockIdx.y * 64, n0 = blockIdx.x * 128;

    const int C = K >> 5;
    float acc[2][8][4];
    #pragma unroll
    for (int i = 0; i < 2; i++)
        #pragma unroll
        for (int j = 0; j < 8; j++)
            #pragma unroll
            for (int q = 0; q < 4; q++) acc[i][j][q] = 0.f;

    auto loadst = [&](int c, int s) {
        int k0 = c << 5;
        uint32_t sbase = su + s * STG64M;
        #pragma unroll
        for (int i = 0; i < 2; i++) {
            int ch = tid + i * 128;
            int row = ch >> 2, c16 = ch & 3;
            uint32_t so = sbase + row * 80 + c16 * 16;
            long ka = (long)(m0 + row) * K + k0 + c16 * 8;
            cpasync16(so,          Ah + ka);
            cpasync16(so + M64A2,  Al + ka);
        }
        #pragma unroll
        for (int i = 0; i < 4; i++) {
            int ch = tid + i * 128;
            int row = ch >> 2, c16 = ch & 3;
            uint32_t so = sbase + 2 * M64A2 + row * 80 + c16 * 16;
            long kb = (long)(n0 + row) * K + k0 + c16 * 8;
            cpasync16(so,          Bh + kb);
            cpasync16(so + M64B2,  Bl + kb);
        }
        asm volatile("cp.async.commit_group;" ::: "memory");
    };

    auto compute = [&](int s) {
        uint32_t tb = su + s * STG64M;
        #pragma unroll
        for (int kk = 0; kk < 2; kk++) {
            int kb = kk * 32;
            uint32_t ah[2][4], al[2][4];
            #pragma unroll
            for (int mt = 0; mt < 2; mt++) {
                uint32_t ad = tb + (wm * 32 + mt * 16 + (lane & 15)) * 80
                              + kb + ((lane >> 4) * 16);
                ldmx4(ah[mt], ad);
                ldmx4(al[mt], ad + M64A2);
            }
            uint32_t bh[2][4], bl[2][4];
            uint32_t bbase = tb + 2 * M64A2
                           + (wn * 64 + (lane >> 4) * 8 + (lane & 7)) * 80
                           + kb + (((lane >> 3) & 1) * 16);
            ldmx4(bh[0], bbase);
            ldmx4(bl[0], bbase + M64B2);
            #pragma unroll
            for (int p = 0; p < 4; p++) {
                int cur = p & 1;
                if (p < 3) {
                    uint32_t bd = bbase + (p + 1) * 16 * 80;
                    ldmx4(bh[cur ^ 1], bd);
                    ldmx4(bl[cur ^ 1], bd + M64B2);
                }
                #pragma unroll
                for (int half = 0; half < 2; half++)
                    #pragma unroll
                    for (int mt = 0; mt < 2; mt++)
                        mma16816(acc[mt][p * 2 + half], ah[mt],
                                 bh[cur][half * 2], bh[cur][half * 2 + 1]);
                #pragma unroll
                for (int half = 0; half < 2; half++)
                    #pragma unroll
                    for (int mt = 0; mt < 2; mt++)
                        mma16816(acc[mt][p * 2 + half], ah[mt],
                                 bl[cur][half * 2], bl[cur][half * 2 + 1]);
                #pragma unroll
                for (int half = 0; half < 2; half++)
                    #pragma unroll
                    for (int mt = 0; mt < 2; mt++)
                        mma16816(acc[mt][p * 2 + half], al[mt],
                                 bh[cur][half * 2], bh[cur][half * 2 + 1]);
            }
        }
    };

    loadst(0, 0);
    for (int c = 0; c < C; c++) {
        if (c + 1 < C) {
            loadst(c + 1, (c + 1) & 1);
            asm volatile("cp.async.wait_group 1;" ::: "memory");
        } else {
            asm volatile("cp.async.wait_group 0;" ::: "memory");
        }
        __syncthreads();
        compute(c & 1);
        __syncthreads();
    }

    float* Cs = (float*)smem_;   // [64][132]
    {
        int gr = lane >> 2, gc = (lane & 3) * 2;
        #pragma unroll
        for (int mt = 0; mt < 2; mt++)
            #pragma unroll
            for (int nt = 0; nt < 8; nt++) {
                int row = wm * 32 + mt * 16 + gr;
                int col = wn * 64 + nt * 8 + gc;
                Cs[row * 132 + col]           = acc[mt][nt][0];
                Cs[row * 132 + col + 1]       = acc[mt][nt][1];
                Cs[(row + 8) * 132 + col]     = acc[mt][nt][2];
                Cs[(row + 8) * 132 + col + 1] = acc[mt][nt][3];
            }
    }
    __syncthreads();

    for (int idx = tid; idx < 64 * 32; idx += 128) {
        int rr = idx >> 5, c4 = (idx & 31) << 2;
        float4 vv = *(const float4*)(Cs + rr * 132 + c4);
        if (mode == 0) {
            *(float4*)(outF + (long)(m0 + rr) * N + n0 + c4) = vv;
        } else {
            float v[4] = {vv.x, vv.y, vv.z, vv.w};
            if (bias) {
                float4 bb = *(const float4*)(bias + n0 + c4);
                v[0] += bb.x; v[1] += bb.y; v[2] += bb.z; v[3] += bb.w;
            }
            store_hl4(outH, outL, (long)(m0 + rr) * N + n0 + c4, v);
        }
    }
}

// --------------------------- flash attention (R14) ---------------------------
#define QPITCH 144
#define VPITCH 272
#define QS_OFF 0
#define QSB 18432
#define KS_OFF (2*QSB)
#define KSTG (2*QSB)
#define VS_OFF (KS_OFF + 2*KSTG)
#define VSB 17408
#define VSTG (2*VSB)
#define FSMEM (VS_OFF + 2*VSTG)    // 180224

__global__ void __launch_bounds__(256, 1) flash_kernel(
    const bf16* __restrict__ qh, const bf16* __restrict__ ql,
    const bf16* __restrict__ kh, const bf16* __restrict__ kl,
    const bf16* __restrict__ vth, const bf16* __restrict__ vtl,
    const float* __restrict__ amask,
    bf16* __restrict__ ch, bf16* __restrict__ cl)
{
    uint32_t su = smem_u32(smem_);
    int tid = threadIdx.x, w = tid >> 5, lane = tid & 31;
    int z = blockIdx.y;
    int b = z / HH, h = z - b * HH;
    int q0 = blockIdx.x * 128;
    const bf16* Qh = qh + (long)z * SS * DKK;
    const bf16* Ql = ql + (long)z * SS * DKK;
    const bf16* Kh = kh + (long)z * SS * DKK;
    const bf16* Kl = kl + (long)z * SS * DKK;
    const bf16* Vh = vth + (long)z * DKK * SS;
    const bf16* Vl = vtl + (long)z * DKK * SS;

    for (int i = tid; i < 1024; i += 256) {
        int r = i >> 3, c = i & 7;
        uint32_t so = su + QS_OFF + r * QPITCH + c * 16;
        long go = (long)(q0 + r) * DKK + c * 8;
        cpasync16(so,        Qh + go);
        cpasync16(so + QSB,  Ql + go);
    }
    auto loadKV = [&](int kt, int s) {
        for (int i = tid; i < 1024; i += 256) {
            int r = i >> 3, c = i & 7;
            uint32_t so = su + KS_OFF + s * KSTG + r * QPITCH + c * 16;
            long go = (long)(kt * 128 + r) * DKK + c * 8;
            cpasync16(so,        Kh + go);
            cpasync16(so + QSB,  Kl + go);
        }
        for (int i = tid; i < 1024; i += 256) {
            int r = i >> 4, c = i & 15;
            uint32_t so = su + VS_OFF + s * VSTG + r * VPITCH + c * 16;
            long go = (long)r * SS + kt * 128 + c * 8;
            cpasync16(so,        Vh + go);
            cpasync16(so + VSB,  Vl + go);
        }
        asm volatile("cp.async.commit_group;" ::: "memory");
    };
    loadKV(0, 0);

    float acc_o[8][4];
    #pragma unroll
    for (int j = 0; j < 8; j++)
        #pragma unroll
        for (int q = 0; q < 4; q++) acc_o[j][q] = 0.f;
    float rm[2] = {-INFINITY, -INFINITY};
    float rl[2] = {0.f, 0.f};
    int gr = lane >> 2, gc2 = (lane & 3) * 2;

    for (int kt = 0; kt < 4; kt++) {
        int s = kt & 1;
        asm volatile("cp.async.wait_group 0;" ::: "memory");
        __syncthreads();
        if (kt + 1 < 4) loadKV(kt + 1, s ^ 1);

        float accs[16][4];
        #pragma unroll
        for (int j = 0; j < 16; j++)
            #pragma unroll
            for (int q = 0; q < 4; q++) accs[j][q] = 0.f;
        uint32_t kbase = su + KS_OFF + s * KSTG;
        #pragma unroll
        for (int kb = 0; kb < 4; kb++) {
            uint32_t aqh[4], aql[4];
            uint32_t ad = su + QS_OFF + (w * 16 + (lane & 15)) * QPITCH
                          + kb * 32 + ((lane >> 4) * 16);
            ldmx4(aqh, ad);
            ldmx4(aql, ad + QSB);
            uint32_t bhf[2][4], blf[2][4];
            uint32_t bd0 = kbase + ((lane >> 4) * 8 + (lane & 7)) * QPITCH
                           + kb * 32 + (((lane >> 3) & 1) * 16);
            ldmx4(bhf[0], bd0);
            ldmx4(blf[0], bd0 + QSB);
            #pragma unroll
            for (int pr = 0; pr < 8; pr++) {
                int cur = pr & 1;
                if (pr < 7) {
                    uint32_t bd = bd0 + (pr + 1) * 16 * QPITCH;
                    ldmx4(bhf[cur ^ 1], bd);
                    ldmx4(blf[cur ^ 1], bd + QSB);
                }
                #pragma unroll
                for (int hf = 0; hf < 2; hf++)
                    mma16816(accs[pr * 2 + hf], aqh, bhf[cur][hf * 2], bhf[cur][hf * 2 + 1]);
                #pragma unroll
                for (int hf = 0; hf < 2; hf++)
                    mma16816(accs[pr * 2 + hf], aqh, blf[cur][hf * 2], blf[cur][hf * 2 + 1]);
                #pragma unroll
                for (int hf = 0; hf < 2; hf++)
                    mma16816(accs[pr * 2 + hf], aql, bhf[cur][hf * 2], bhf[cur][hf * 2 + 1]);
            }
        }

        const float* mrow = amask + b * SS + kt * 128;
        float tmax0 = -INFINITY, tmax1 = -INFINITY;
        #pragma unroll
        for (int nt = 0; nt < 16; nt++) {
            int c0 = nt * 8 + gc2;
            float m0 = mrow[c0], m1 = mrow[c0 + 1];
            float v0 = accs[nt][0] * SCALE, v1 = accs[nt][1] * SCALE;
            float v2 = accs[nt][2] * SCALE, v3 = accs[nt][3] * SCALE;
            if (m0 == 0.f) { v0 = -1e9f; v2 = -1e9f; }
            if (m1 == 0.f) { v1 = -1e9f; v3 = -1e9f; }
            accs[nt][0] = v0; accs[nt][1] = v1; accs[nt][2] = v2; accs[nt][3] = v3;
            tmax0 = fmaxf(tmax0, fmaxf(v0, v1));
            tmax1 = fmaxf(tmax1, fmaxf(v2, v3));
        }
        tmax0 = fmaxf(tmax0, __shfl_xor_sync(0xffffffffu, tmax0, 1));
        tmax0 = fmaxf(tmax0, __shfl_xor_sync(0xffffffffu, tmax0, 2));
        tmax1 = fmaxf(tmax1, __shfl_xor_sync(0xffffffffu, tmax1, 1));
        tmax1 = fmaxf(tmax1, __shfl_xor_sync(0xffffffffu, tmax1, 2));
        float nm0 = fmaxf(rm[0], tmax0), nm1 = fmaxf(rm[1], tmax1);
        float al0 = __expf(rm[0] - nm0), al1 = __expf(rm[1] - nm1);
        rm[0] = nm0; rm[1] = nm1;
        #pragma unroll
        for (int j = 0; j < 8; j++) {
            acc_o[j][0] *= al0; acc_o[j][1] *= al0;
            acc_o[j][2] *= al1; acc_o[j][3] *= al1;
        }
        rl[0] *= al0; rl[1] *= al1;

        uint32_t vbase = su + VS_OFF + s * VSTG;
        float rs0 = 0.f, rs1 = 0.f;
        #pragma unroll
        for (int kc = 0; kc < 8; kc++) {
            float p[2][4];
            #pragma unroll
            for (int hf = 0; hf < 2; hf++) {
                int nt = kc * 2 + hf;
                p[hf][0] = __expf(accs[nt][0] - nm0);
                p[hf][1] = __expf(accs[nt][1] - nm0);
                p[hf][2] = __expf(accs[nt][2] - nm1);
                p[hf][3] = __expf(accs[nt][3] - nm1);
                rs0 += p[hf][0] + p[hf][1];
                rs1 += p[hf][2] + p[hf][3];
            }
            uint32_t pah[4], pal[4];
            #pragma unroll
            for (int hf = 0; hf < 2; hf++) {
                float h0 = __bfloat162float(__float2bfloat16_rn(p[hf][0]));
                float h1 = __bfloat162float(__float2bfloat16_rn(p[hf][1]));
                float h2 = __bfloat162float(__float2bfloat16_rn(p[hf][2]));
                float h3 = __bfloat162float(__float2bfloat16_rn(p[hf][3]));
                pah[hf * 2]     = packbf2(h0, h1);
                pah[hf * 2 + 1] = packbf2(h2, h3);
                pal[hf * 2]     = packbf2(p[hf][0] - h0, p[hf][1] - h1);
                pal[hf * 2 + 1] = packbf2(p[hf][2] - h2, p[hf][3] - h3);
            }
            uint32_t vhf[2][4], vlf[2][4];
            uint32_t vd0 = vbase + ((lane >> 4) * 8 + (lane & 7)) * VPITCH
                           + kc * 32 + (((lane >> 3) & 1) * 16);
            ldmx4(vhf[0], vd0);
            ldmx4(vlf[0], vd0 + VSB);
            #pragma unroll
            for (int vp = 0; vp < 4; vp++) {
                int cur = vp & 1;
                if (vp < 3) {
                    uint32_t vd = vd0 + (vp + 1) * 16 * VPITCH;
                    ldmx4(vhf[cur ^ 1], vd);
                    ldmx4(vlf[cur ^ 1], vd + VSB);
                }
                #pragma unroll
                for (int hf = 0; hf < 2; hf++)
                    mma16816(acc_o[vp * 2 + hf], pah, vhf[cur][hf * 2], vhf[cur][hf * 2 + 1]);
                #pragma unroll
                for (int hf = 0; hf < 2; hf++)
                    mma16816(acc_o[vp * 2 + hf], pah, vlf[cur][hf * 2], vlf[cur][hf * 2 + 1]);
                #pragma unroll
                for (int hf = 0; hf < 2; hf++)
                    mma16816(acc_o[vp * 2 + hf], pal, vhf[cur][hf * 2], vhf[cur][hf * 2 + 1]);
            }
        }
        rl[0] += rs0;
        rl[1] += rs1;
    }
    rl[0] += __shfl_xor_sync(0xffffffffu, rl[0], 1);
    rl[0] += __shfl_xor_sync(0xffffffffu, rl[0], 2);
    rl[1] += __shfl_xor_sync(0xffffffffu, rl[1], 1);
    rl[1] += __shfl_xor_sync(0xffffffffu, rl[1], 2);
    __syncthreads();

    float* Cs = (float*)(smem_ + KS_OFF);     // [128][68]
    {
        float inv0 = 1.f / rl[0], inv1 = 1.f / rl[1];
        int r0 = w * 16 + gr;
        #pragma unroll
        for (int no = 0; no < 8; no++) {
            int col = no * 8 + gc2;
            Cs[r0 * 68 + col]           = acc_o[no][0] * inv0;
            Cs[r0 * 68 + col + 1]       = acc_o[no][1] * inv0;
            Cs[(r0 + 8) * 68 + col]     = acc_o[no][2] * inv1;
            Cs[(r0 + 8) * 68 + col + 1] = acc_o[no][3] * inv1;
        }
    }
    __syncthreads();
    for (int idx = tid; idx < 128 * 16; idx += 256) {
        int r = idx >> 4, c4 = (idx & 15) << 2;
        float4 vv = *(const float4*)(Cs + r * 68 + c4);
        float v[4] = {vv.x, vv.y, vv.z, vv.w};
        long dst = ((long)(b * SS + q0 + r)) * DD + h * DKK + c4;
        store_hl4(ch, cl, dst, v);
    }
}

// --------------------------- elementwise kernels -----------------------------
__device__ __forceinline__ float bsum(float v, float* sh) {
    int lane = threadIdx.x & 31, w = threadIdx.x >> 5;
    #pragma unroll
    for (int o = 16; o > 0; o >>= 1) v += __shfl_xor_sync(0xffffffffu, v, o);
    if (lane == 0) sh[w] = v;
    __syncthreads();
    float r = 0.f;
    #pragma unroll
    for (int i = 0; i < 8; i++) r += sh[i];
    __syncthreads();
    return r;
}
__device__ __forceinline__ void wsplit(bf16* H, bf16* L, long i, float v) {
    bf16 h = __float2bfloat16_rn(v);
    H[i] = h;
    L[i] = __float2bfloat16_rn(v - __bfloat162float(h));
}

#define S1 ((long)LL*DD*DD)
#define S2 ((long)LL*FF*DD)
// qkv fused (3*S1) + Wo (S1) + W2 (S2). W1 handled by transpose kernel.
__global__ void cvt_all_kernel(const float* __restrict__ Wq, const float* __restrict__ Wk,
                               const float* __restrict__ Wv, const float* __restrict__ Wo,
                               const float* __restrict__ W2,
                               bf16* __restrict__ qkvh, bf16* __restrict__ qkvl,
                               bf16* __restrict__ woh, bf16* __restrict__ wol,
                               bf16* __restrict__ w2h, bf16* __restrict__ w2l) {
    const long total = 4 * S1 + S2;
    long i = (long)blockIdx.x * 256 + threadIdx.x;
    long stride = (long)gridDim.x * 256;
    for (; i < total; i += stride) {
        long j = i;
        if (j < 3 * S1) {
            int seg = (int)(j / S1);
            long r = j - (long)seg * S1;
            const float* src = (seg == 0) ? Wq : (seg == 1) ? Wk : Wv;
            long l = r / (DD * DD);
            long rem = r - l * (DD * DD);
            long n = rem / DD, k = rem - n * DD;
            long dst = (l * NQKV + seg * DD + n) * DD + k;
            wsplit(qkvh, qkvl, dst, src[r]);
        } else if (j < 4 * S1) {
            long r = j - 3 * S1;
            wsplit(woh, wol, r, Wo[r]);
        } else {
            long r = j - 4 * S1;
            wsplit(w2h, w2l, r, W2[r]);
        }
    }
}

// transpose W1 [l][f][e] -> split [l][e][f], tiled 32x32
__global__ void cvt_w1t_kernel(const float* __restrict__ W1,
                               bf16* __restrict__ th, bf16* __restrict__ tl) {
    __shared__ float s[32][33];
    int l = blockIdx.z;
    int e0 = blockIdx.x * 32, f0 = blockIdx.y * 32;
    int tx = threadIdx.x, ty = threadIdx.y;     // (32, 8)
    const float* src = W1 + (long)l * FF * DD;
    #pragma unroll
    for (int i = 0; i < 4; i++)
        s[ty + i * 8][tx] = src[(long)(f0 + ty + i * 8) * DD + e0 + tx];
    __syncthreads();
    bf16* dh = th + (long)l * DD * FF;
    bf16* dl = tl + (long)l * DD * FF;
    #pragma unroll
    for (int i = 0; i < 4; i++) {
        float v = s[tx][ty + i * 8];
        long o = (long)(e0 + ty + i * 8) * FF + f0 + tx;
        wsplit(dh, dl, o, v);
    }
}

// beff[l][d] = sum_f W2[l][d][f]*b1[l][f] + b2[l][d]
__global__ void beff_kernel(const float* __restrict__ W2, const float* __restrict__ b1,
                            const float* __restrict__ b2, float* __restrict__ beff) {
    __shared__ float sh[8];
    int ld = blockIdx.x;
    int l = ld / DD;
    const float* w = W2 + (long)ld * FF;
    const float* bb = b1 + (long)l * FF;
    float s = 0.f;
    for (int f = threadIdx.x; f < FF; f += 256) s += w[f] * bb[f];
    s = bsum(s, sh);
    if (threadIdx.x == 0) beff[ld] = s + b2[ld];
}

__global__ void embed_ln_kernel(const int* __restrict__ ids, const int* __restrict__ tt,
                                const float* __restrict__ we, const float* __restrict__ pe,
                                const float* __restrict__ te, const float* __restrict__ gamma,
                                const float* __restrict__ beta, float* __restrict__ outF,
                                bf16* __restrict__ outH, bf16* __restrict__ outL) {
    __shared__ float sh[8];
    int m = blockIdx.x, s = m & (SS - 1);
    int id = ids[m], ty = tt[m], t = threadIdx.x;
    float v[3];
    #pragma unroll
    for (int i = 0; i < 3; i++) {
        int d = t + i * 256;
        v[i] = we[(long)id * DD + d] + te[(long)ty * DD + d] + pe[(long)s * DD + d];
    }
    float mu = bsum(v[0] + v[1] + v[2], sh) * (1.f / DD);
    float qs = 0.f;
    #pragma unroll
    for (int i = 0; i < 3; i++) { float d0 = v[i] - mu; qs += d0 * d0; }
    float rstd = rsqrtf(bsum(qs, sh) * (1.f / DD) + 1e-12f);
    #pragma unroll
    for (int i = 0; i < 3; i++) {
        int d = t + i * 256;
        float y = (v[i] - mu) * rstd * gamma[d] + beta[d];
        outF[(long)m * DD + d] = y;
        wsplit(outH, outL, (long)m * DD + d, y);
    }
}

__global__ void ln768_kernel(const float* __restrict__ in, const float* __restrict__ resid,
                             const float* __restrict__ bias, const float* __restrict__ gamma,
                             const float* __restrict__ beta, float* __restrict__ outF,
                             bf16* __restrict__ outH, bf16* __restrict__ outL, float eps) {
    __shared__ float sh[8];
    long m = blockIdx.x;
    int t = threadIdx.x;
    float v[3];
    #pragma unroll
    for (int i = 0; i < 3; i++) {
        int d = t + i * 256;
        float x = in[m * DD + d];
        if (bias) x += bias[d];
        if (resid) x += resid[m * DD + d];
        v[i] = x;
    }
    float mu = bsum(v[0] + v[1] + v[2], sh) * (1.f / DD);
    float qs = 0.f;
    #pragma unroll
    for (int i = 0; i < 3; i++) { float d0 = v[i] - mu; qs += d0 * d0; }
    float rstd = rsqrtf(bsum(qs, sh) * (1.f / DD) + eps);
    #pragma unroll
    for (int i = 0; i < 3; i++) {
        int d = t + i * 256;
        float y = (v[i] - mu) * rstd * gamma[d] + beta[d];
        if (outF) outF[m * DD + d] = y;
        wsplit(outH, outL, m * DD + d, y);
    }
}

// ------------------------------- launch --------------------------------------
extern "C" void kernel_launch(void* const* d_in, const int* in_sizes, int n_in,
                              void* d_out, int out_size) {
    const int*   input_ids = (const int*)  d_in[0];
    const int*   type_ids  = (const int*)  d_in[1];
    const float* amask     = (const float*)d_in[2];
    const float* word_emb  = (const float*)d_in[3];
    const float* pos_emb   = (const float*)d_in[4];
    const float* type_emb  = (const float*)d_in[5];
    const float* emb_g     = (const float*)d_in[6];
    const float* emb_b     = (const float*)d_in[7];
    const float* Wq = (const float*)d_in[8];  const float* bq = (const float*)d_in[9];
    const float* Wk = (const float*)d_in[10]; const float* bk = (const float*)d_in[11];
    const float* Wv = (const float*)d_in[12]; const float* bv = (const float*)d_in[13];
    const float* Wo = (const float*)d_in[14]; const float* bo = (const float*)d_in[15];
    const float* ag = (const float*)d_in[16]; const float* ab = (const float*)d_in[17];
    const float* W1 = (const float*)d_in[18]; const float* b1 = (const float*)d_in[19];
    const float* W2 = (const float*)d_in[20]; const float* b2 = (const float*)d_in[21];
    const float* fg = (const float*)d_in[22]; const float* fb = (const float*)d_in[23];

    static int smem_set = 0;
    if (!smem_set) {
        cudaFuncSetAttribute(mm_kernel, cudaFuncAttributeMaxDynamicSharedMemorySize, MMSMEM);
        cudaFuncSetAttribute(mm64m_kernel, cudaFuncAttributeMaxDynamicSharedMemorySize, MM64MSMEM);
        cudaFuncSetAttribute(flash_kernel, cudaFuncAttributeMaxDynamicSharedMemorySize, FSMEM);
        smem_set = 1;
    }

    float *x, *t, *beff;
    bf16 *xh, *xl, *ah, *al, *qh, *ql, *kh, *kl, *vth, *vtl, *ch, *cl;
    bf16 *qkvh, *qkvl, *woh, *wol, *w1th, *w1tl, *w2h, *w2l, *weffh, *weffl;
    cudaGetSymbolAddress((void**)&x, g_x);     cudaGetSymbolAddress((void**)&t, g_t);
    cudaGetSymbolAddress((void**)&beff, g_beff);
    cudaGetSymbolAddress((void**)&xh, g_xh);   cudaGetSymbolAddress((void**)&xl, g_xl);
    cudaGetSymbolAddress((void**)&ah, g_ah);   cudaGetSymbolAddress((void**)&al, g_al);
    cudaGetSymbolAddress((void**)&qh, g_qh);   cudaGetSymbolAddress((void**)&ql, g_ql);
    cudaGetSymbolAddress((void**)&kh, g_kh);   cudaGetSymbolAddress((void**)&kl, g_kl);
    cudaGetSymbolAddress((void**)&vth, g_vth); cudaGetSymbolAddress((void**)&vtl, g_vtl);
    cudaGetSymbolAddress((void**)&ch, g_ch);   cudaGetSymbolAddress((void**)&cl, g_cl);
    cudaGetSymbolAddress((void**)&qkvh, g_wqkvh); cudaGetSymbolAddress((void**)&qkvl, g_wqkvl);
    cudaGetSymbolAddress((void**)&woh, g_woh); cudaGetSymbolAddress((void**)&wol, g_wol);
    cudaGetSymbolAddress((void**)&w1th, g_w1th); cudaGetSymbolAddress((void**)&w1tl, g_w1tl);
    cudaGetSymbolAddress((void**)&w2h, g_w2h); cudaGetSymbolAddress((void**)&w2l, g_w2l);
    cudaGetSymbolAddress((void**)&weffh, g_weffh); cudaGetSymbolAddress((void**)&weffl, g_weffl);

    cvt_all_kernel<<<8192, 256>>>(Wq, Wk, Wv, Wo, W2,
                                  qkvh, qkvl, woh, wol, w2h, w2l);
    cvt_w1t_kernel<<<dim3(DD / 32, FF / 32, LL), dim3(32, 8)>>>(W1, w1th, w1tl);
    beff_kernel<<<LL * DD, 256>>>(W2, b1, b2, beff);

    // Weff = W2 @ W1 for all layers in one z-batched launch (hi/lo output)
    mm_kernel<<<dim3(6, 6, LL), 128, MMSMEM>>>(w2h, w2l, (long)DD * FF,
        w1th, w1tl, (long)DD * FF, nullptr, nullptr, nullptr, 1.f,
        DD, DD, FF, nullptr, weffh, weffl, nullptr, nullptr, nullptr, nullptr,
        (long)DD * DD, 1);

    embed_ln_kernel<<<MTOK, 256>>>(input_ids, type_ids, word_emb, pos_emb,
                                   type_emb, emb_g, emb_b, x, xh, xl);

    for (int l = 0; l < LL; l++) {
        const bf16* qkh = qkvh + (long)l * NQKV * DD;
        const bf16* qkl = qkvl + (long)l * NQKV * DD;
        // fused QKV
        mm_kernel<<<dim3(18, 32), 128, MMSMEM>>>(xh, xl, 0, qkh, qkl, 0,
            bq + l * DD, bk + l * DD, bv + l * DD, 1.f, MTOK, NQKV, DD,
            nullptr, qh, ql, kh, kl, vth, vtl, 0, 5);
        // fused attention
        flash_kernel<<<dim3(4, NHB), 256, FSMEM>>>(qh, ql, kh, kl, vth, vtl,
                                                   amask, ch, cl);
        // O projection -> fp32 t
        mm64m_kernel<<<dim3(6, 64), 128, MM64MSMEM>>>(ch, cl,
            woh + (long)l * DD * DD, wol + (long)l * DD * DD, nullptr,
            MTOK, DD, DD, t, nullptr, nullptr, 0);
        ln768_kernel<<<MTOK, 256>>>(t, x, bo + l * DD, ag + l * DD, ab + l * DD,
                                    nullptr, ah, al, 1e-5f);
        // FFN collapsed: y = a @ Weff^T -> fp32 t
        mm64m_kernel<<<dim3(6, 64), 128, MM64MSMEM>>>(ah, al,
            weffh + (long)l * DD * DD, weffl + (long)l * DD * DD, nullptr,
            MTOK, DD, DD, t, nullptr, nullptr, 0);
        ln768_kernel<<<MTOK, 256>>>(t, nullptr, beff + l * DD, fg + l * DD,
                                    fb + l * DD, x, xh, xl, 1e-5f);
    }

    cudaMemcpyAsync(d_out, x, (size_t)MTOK * DD * sizeof(float),
                    cudaMemcpyDeviceToDevice);
}

// round 17
// speedup vs baseline: 1.7752x; 1.0148x over previous
#include <cuda_runtime.h>
#include <cuda_bf16.h>
#include <stdint.h>
#include <math.h>

#define BB 8
#define SS 512
#define DD 768
#define HH 12
#define DKK 64
#define FF 3072
#define LL 12
#define MTOK (BB*SS)
#define NHB (BB*HH)
#define SCALE 0.125f
#define NQKV 2304

typedef __nv_bfloat16 bf16;

// ------------------------------- scratch -----------------------------------
__device__ __align__(256) float g_x[MTOK*DD];
__device__ __align__(256) float g_t[MTOK*DD];
__device__ __align__(256) bf16 g_xh[MTOK*DD], g_xl[MTOK*DD];
__device__ __align__(256) bf16 g_ah[MTOK*DD], g_al[MTOK*DD];
__device__ __align__(256) bf16 g_qh[MTOK*DD], g_ql[MTOK*DD];
__device__ __align__(256) bf16 g_kh[MTOK*DD], g_kl[MTOK*DD];
__device__ __align__(256) bf16 g_vth[MTOK*DD], g_vtl[MTOK*DD];   // V^T [b,h,dk,s]
__device__ __align__(256) bf16 g_ch[MTOK*DD], g_cl[MTOK*DD];
__device__ __align__(256) bf16 g_wqkvh[(long)LL*NQKV*DD], g_wqkvl[(long)LL*NQKV*DD];
__device__ __align__(256) bf16 g_woh[LL*DD*DD], g_wol[LL*DD*DD];
__device__ __align__(256) bf16 g_w1th[(long)LL*DD*FF], g_w1tl[(long)LL*DD*FF]; // W1^T [l][e][f]
__device__ __align__(256) bf16 g_w2h[(long)LL*DD*FF], g_w2l[(long)LL*DD*FF];   // W2 [l][d][f]
__device__ __align__(256) bf16 g_weffh[LL*DD*DD], g_weffl[LL*DD*DD];           // W2@W1 [l][d][e]
__device__ __align__(256) float g_beff[LL*DD];

// ----------------------------- helpers --------------------------------------
__device__ __forceinline__ uint32_t smem_u32(const void* p) {
    uint32_t a;
    asm("{ .reg .u64 t; cvta.to.shared.u64 t, %1; cvt.u32.u64 %0, t; }"
        : "=r"(a) : "l"(p));
    return a;
}
__device__ __forceinline__ void cpasync16(uint32_t saddr, const void* gaddr) {
    asm volatile("cp.async.ca.shared.global [%0], [%1], 16;"
                 :: "r"(saddr), "l"(gaddr) : "memory");
}
__device__ __forceinline__ void ldmx4(uint32_t* r, uint32_t addr) {
    asm volatile("ldmatrix.sync.aligned.m8n8.x4.shared.b16 {%0,%1,%2,%3}, [%4];"
                 : "=r"(r[0]), "=r"(r[1]), "=r"(r[2]), "=r"(r[3]) : "r"(addr));
}
__device__ __forceinline__ void mma16816(float* c, const uint32_t* a,
                                         uint32_t b0, uint32_t b1) {
    asm volatile(
        "mma.sync.aligned.m16n8k16.row.col.f32.bf16.bf16.f32 "
        "{%0,%1,%2,%3}, {%4,%5,%6,%7}, {%8,%9}, {%0,%1,%2,%3};"
        : "+f"(c[0]), "+f"(c[1]), "+f"(c[2]), "+f"(c[3])
        : "r"(a[0]), "r"(a[1]), "r"(a[2]), "r"(a[3]), "r"(b0), "r"(b1));
}
__device__ __forceinline__ void store_hl4(bf16* __restrict__ H, bf16* __restrict__ L,
                                          long dst, const float* v) {
    union { bf16 b[4]; uint2 u; } uh, ul;
    #pragma unroll
    for (int i = 0; i < 4; i++) {
        bf16 h = __float2bfloat16_rn(v[i]);
        uh.b[i] = h;
        ul.b[i] = __float2bfloat16_rn(v[i] - __bfloat162float(h));
    }
    *(uint2*)(H + dst) = uh.u;
    *(uint2*)(L + dst) = ul.u;
}
__device__ __forceinline__ uint32_t packbf2(float a, float b) {
    __nv_bfloat162 t = __floats2bfloat162_rn(a, b);
    return *(uint32_t*)&t;
}

// ------------------------- mm_kernel (128x128, 4 warps) ----------------------
#define MATB 10240
#define STGB (4*MATB)
#define MMSMEM 81920

extern __shared__ __align__(16) char smem_[];

__global__ void __launch_bounds__(128, 2) mm_kernel(
    const bf16* __restrict__ Ah, const bf16* __restrict__ Al, long sA,
    const bf16* __restrict__ Bh, const bf16* __restrict__ Bl, long sB,
    const float* __restrict__ bias, const float* __restrict__ bias2,
    const float* __restrict__ bias3, float alpha, int M, int N, int K,
    float* __restrict__ outF, bf16* __restrict__ o1H, bf16* __restrict__ o1L,
    bf16* __restrict__ o2H, bf16* __restrict__ o2L,
    bf16* __restrict__ o3H, bf16* __restrict__ o3L, long sC, int mode)
{
    uint32_t su = smem_u32(smem_);
    int tid = threadIdx.x, wid = tid >> 5, lane = tid & 31;
    int wm = wid & 1, wn = wid >> 1;
    int z = blockIdx.z;
    Ah += (long)z * sA;  Al += (long)z * sA;
    Bh += (long)z * sB;  Bl += (long)z * sB;
    int m0 = blockIdx.y * 128, n0 = blockIdx.x * 128;

    const int C = K >> 5;
    float acc[4][8][4];
    #pragma unroll
    for (int i = 0; i < 4; i++)
        #pragma unroll
        for (int j = 0; j < 8; j++)
            #pragma unroll
            for (int q = 0; q < 4; q++) acc[i][j][q] = 0.f;

    auto loadst = [&](int c, int s) {
        int k0 = c << 5;
        uint32_t sbase = su + s * STGB;
        #pragma unroll
        for (int i = 0; i < 4; i++) {
            int ch = tid + i * 128;
            int row = ch >> 2, c16 = ch & 3;
            uint32_t so = sbase + row * 80 + c16 * 16;
            long ka = (long)(m0 + row) * K + k0 + c16 * 8;
            long kb = (long)(n0 + row) * K + k0 + c16 * 8;
            cpasync16(so,            Ah + ka);
            cpasync16(so + MATB,     Al + ka);
            cpasync16(so + 2 * MATB, Bh + kb);
            cpasync16(so + 3 * MATB, Bl + kb);
        }
        asm volatile("cp.async.commit_group;" ::: "memory");
    };

    auto compute = [&](int s) {
        uint32_t tb = su + s * STGB;
        #pragma unroll
        for (int kk = 0; kk < 2; kk++) {
            int kb = kk * 32;
            uint32_t ah[4][4], al[4][4];
            #pragma unroll
            for (int mt = 0; mt < 4; mt++) {
                uint32_t ad = tb + (wm * 64 + mt * 16 + (lane & 15)) * 80
                              + kb + ((lane >> 4) * 16);
                ldmx4(ah[mt], ad);
                ldmx4(al[mt], ad + MATB);
            }
            uint32_t bh[2][4], bl[2][4];
            uint32_t bbase = tb + 2 * MATB
                           + (wn * 64 + (lane >> 4) * 8 + (lane & 7)) * 80
                           + kb + (((lane >> 3) & 1) * 16);
            ldmx4(bh[0], bbase);
            ldmx4(bl[0], bbase + MATB);
            #pragma unroll
            for (int p = 0; p < 4; p++) {
                int cur = p & 1;
                if (p < 3) {
                    uint32_t bd = bbase + (p + 1) * 16 * 80;
                    ldmx4(bh[cur ^ 1], bd);
                    ldmx4(bl[cur ^ 1], bd + MATB);
                }
                #pragma unroll
                for (int half = 0; half < 2; half++)
                    #pragma unroll
                    for (int mt = 0; mt < 4; mt++)
                        mma16816(acc[mt][p * 2 + half], ah[mt],
                                 bh[cur][half * 2], bh[cur][half * 2 + 1]);
                #pragma unroll
                for (int half = 0; half < 2; half++)
                    #pragma unroll
                    for (int mt = 0; mt < 4; mt++)
                        mma16816(acc[mt][p * 2 + half], ah[mt],
                                 bl[cur][half * 2], bl[cur][half * 2 + 1]);
                #pragma unroll
                for (int half = 0; half < 2; half++)
                    #pragma unroll
                    for (int mt = 0; mt < 4; mt++)
                        mma16816(acc[mt][p * 2 + half], al[mt],
                                 bh[cur][half * 2], bh[cur][half * 2 + 1]);
            }
        }
    };

    loadst(0, 0);
    for (int c = 0; c < C; c++) {
        if (c + 1 < C) {
            loadst(c + 1, (c + 1) & 1);
            asm volatile("cp.async.wait_group 1;" ::: "memory");
        } else {
            asm volatile("cp.async.wait_group 0;" ::: "memory");
        }
        __syncthreads();
        compute(c & 1);
        __syncthreads();
    }

    float* Cs = (float*)smem_;   // [128][132]
    {
        int gr = lane >> 2, gc = (lane & 3) * 2;
        #pragma unroll
        for (int mt = 0; mt < 4; mt++)
            #pragma unroll
            for (int nt = 0; nt < 8; nt++) {
                int row = wm * 64 + mt * 16 + gr;
                int col = wn * 64 + nt * 8 + gc;
                Cs[row * 132 + col]           = acc[mt][nt][0];
                Cs[row * 132 + col + 1]       = acc[mt][nt][1];
                Cs[(row + 8) * 132 + col]     = acc[mt][nt][2];
                Cs[(row + 8) * 132 + col + 1] = acc[mt][nt][3];
            }
    }
    __syncthreads();

    if (mode == 0) {
        for (int idx = tid; idx < 128 * 32; idx += 128) {
            int rr = idx >> 5, c4 = (idx & 31) << 2;
            float4 vv = *(const float4*)(Cs + rr * 132 + c4);
            vv.x *= alpha; vv.y *= alpha; vv.z *= alpha; vv.w *= alpha;
            *(float4*)(outF + (long)z * sC + (long)(m0 + rr) * N + n0 + c4) = vv;
        }
    } else if (mode == 1) {
        for (int idx = tid; idx < 128 * 32; idx += 128) {
            int rr = idx >> 5, c4 = (idx & 31) << 2;
            float4 vv = *(const float4*)(Cs + rr * 132 + c4);
            float v[4] = {vv.x, vv.y, vv.z, vv.w};
            if (bias) {
                float4 bb = *(const float4*)(bias + n0 + c4);
                v[0] += bb.x; v[1] += bb.y; v[2] += bb.z; v[3] += bb.w;
            }
            store_hl4(o1H, o1L, (long)z * sC + (long)(m0 + rr) * N + n0 + c4, v);
        }
    } else {
        int seg = n0 / DD;            // 0:Q 1:K 2:V
        int nl0 = n0 - seg * DD;
        if (seg < 2) {
            const float* bb = (seg == 0) ? bias : bias2;
            bf16* H = (seg == 0) ? o1H : o2H;
            bf16* L = (seg == 0) ? o1L : o2L;
            for (int idx = tid; idx < 128 * 32; idx += 128) {
                int rr = idx >> 5, c4 = (idx & 31) << 2;
                float4 vv = *(const float4*)(Cs + rr * 132 + c4);
                float4 bbv = *(const float4*)(bb + nl0 + c4);
                float v[4] = {vv.x + bbv.x, vv.y + bbv.y, vv.z + bbv.z, vv.w + bbv.w};
                int mg = m0 + rr, b = mg >> 9, sI = mg & 511;
                int ng = nl0 + c4, hh = ng >> 6, dk = ng & 63;
                long dst = (((long)(b * HH + hh) * SS + sI) << 6) + dk;
                store_hl4(H, L, dst, v);
            }
        } else {
            int b = m0 >> 9, s0v = m0 & 511;
            for (int idx = tid; idx < 128 * 32; idx += 128) {
                int n = idx >> 5, rg = (idx & 31) << 2;
                int ng = nl0 + n, hh = ng >> 6, dk = ng & 63;
                float badd = bias3[ng];
                float v[4];
                #pragma unroll
                for (int i = 0; i < 4; i++) v[i] = Cs[(rg + i) * 132 + n] + badd;
                long dst = (((long)(b * HH + hh) * DKK + dk) << 9) + s0v + rg;
                store_hl4(o3H, o3L, dst, v);
            }
        }
    }
}

// ---------------------- mm64m_kernel (64x128, 4 warps, z-batched) ------------
#define M64A2 5120
#define M64B2 10240
#define STG64M (2*M64A2 + 2*M64B2)
#define MM64MSMEM 61440

__global__ void __launch_bounds__(128, 2) mm64m_kernel(
    const bf16* __restrict__ Ah, const bf16* __restrict__ Al, long sA,
    const bf16* __restrict__ Bh, const bf16* __restrict__ Bl, long sB,
    const float* __restrict__ bias, int M, int N, int K,
    float* __restrict__ outF, bf16* __restrict__ outH, bf16* __restrict__ outL,
    long sC, int mode)
{
    uint32_t su = smem_u32(smem_);
    int tid = threadIdx.x, wid = tid >> 5, lane = tid & 31;
    int wm = wid & 1, wn = wid >> 1;
    int z = blockIdx.z;
    Ah += (long)z * sA;  Al += (long)z * sA;
    Bh += (long)z * sB;  Bl += (long)z * sB;
    int m0 = blockIdx.y * 64, n0 = blockIdx.x * 128;

    const int C = K >> 5;
    float acc[2][8][4];
    #pragma unroll
    for (int i = 0; i < 2; i++)
        #pragma unroll
        for (int j = 0; j < 8; j++)
            #pragma unroll
            for (int q = 0; q < 4; q++) acc[i][j][q] = 0.f;

    auto loadst = [&](int c, int s) {
        int k0 = c << 5;
        uint32_t sbase = su + s * STG64M;
        #pragma unroll
        for (int i = 0; i < 2; i++) {
            int ch = tid + i * 128;
            int row = ch >> 2, c16 = ch & 3;
            uint32_t so = sbase + row * 80 + c16 * 16;
            long ka = (long)(m0 + row) * K + k0 + c16 * 8;
            cpasync16(so,          Ah + ka);
            cpasync16(so + M64A2,  Al + ka);
        }
        #pragma unroll
        for (int i = 0; i < 4; i++) {
            int ch = tid + i * 128;
            int row = ch >> 2, c16 = ch & 3;
            uint32_t so = sbase + 2 * M64A2 + row * 80 + c16 * 16;
            long kb = (long)(n0 + row) * K + k0 + c16 * 8;
            cpasync16(so,          Bh + kb);
            cpasync16(so + M64B2,  Bl + kb);
        }
        asm volatile("cp.async.commit_group;" ::: "memory");
    };

    auto compute = [&](int s) {
        uint32_t tb = su + s * STG64M;
        #pragma unroll
        for (int kk = 0; kk < 2; kk++) {
            int kb = kk * 32;
            uint32_t ah[2][4], al[2][4];
            #pragma unroll
            for (int mt = 0; mt < 2; mt++) {
                uint32_t ad = tb + (wm * 32 + mt * 16 + (lane & 15)) * 80
                              + kb + ((lane >> 4) * 16);
                ldmx4(ah[mt], ad);
                ldmx4(al[mt], ad + M64A2);
            }
            uint32_t bh[2][4], bl[2][4];
            uint32_t bbase = tb + 2 * M64A2
                           + (wn * 64 + (lane >> 4) * 8 + (lane & 7)) * 80
                           + kb + (((lane >> 3) & 1) * 16);
            ldmx4(bh[0], bbase);
            ldmx4(bl[0], bbase + M64B2);
            #pragma unroll
            for (int p = 0; p < 4; p++) {
                int cur = p & 1;
                if (p < 3) {
                    uint32_t bd = bbase + (p + 1) * 16 * 80;
                    ldmx4(bh[cur ^ 1], bd);
                    ldmx4(bl[cur ^ 1], bd + M64B2);
                }
                #pragma unroll
                for (int half = 0; half < 2; half++)
                    #pragma unroll
                    for (int mt = 0; mt < 2; mt++)
                        mma16816(acc[mt][p * 2 + half], ah[mt],
                                 bh[cur][half * 2], bh[cur][half * 2 + 1]);
                #pragma unroll
                for (int half = 0; half < 2; half++)
                    #pragma unroll
                    for (int mt = 0; mt < 2; mt++)
                        mma16816(acc[mt][p * 2 + half], ah[mt],
                                 bl[cur][half * 2], bl[cur][half * 2 + 1]);
                #pragma unroll
                for (int half = 0; half < 2; half++)
                    #pragma unroll
                    for (int mt = 0; mt < 2; mt++)
                        mma16816(acc[mt][p * 2 + half], al[mt],
                                 bh[cur][half * 2], bh[cur][half * 2 + 1]);
            }
        }
    };

    loadst(0, 0);
    for (int c = 0; c < C; c++) {
        if (c + 1 < C) {
            loadst(c + 1, (c + 1) & 1);
            asm volatile("cp.async.wait_group 1;" ::: "memory");
        } else {
            asm volatile("cp.async.wait_group 0;" ::: "memory");
        }
        __syncthreads();
        compute(c & 1);
        __syncthreads();
    }

    float* Cs = (float*)smem_;   // [64][132]
    {
        int gr = lane >> 2, gc = (lane & 3) * 2;
        #pragma unroll
        for (int mt = 0; mt < 2; mt++)
            #pragma unroll
            for (int nt = 0; nt < 8; nt++) {
                int row = wm * 32 + mt * 16 + gr;
                int col = wn * 64 + nt * 8 + gc;
                Cs[row * 132 + col]           = acc[mt][nt][0];
                Cs[row * 132 + col + 1]       = acc[mt][nt][1];
                Cs[(row + 8) * 132 + col]     = acc[mt][nt][2];
                Cs[(row + 8) * 132 + col + 1] = acc[mt][nt][3];
            }
    }
    __syncthreads();

    for (int idx = tid; idx < 64 * 32; idx += 128) {
        int rr = idx >> 5, c4 = (idx & 31) << 2;
        float4 vv = *(const float4*)(Cs + rr * 132 + c4);
        if (mode == 0) {
            *(float4*)(outF + (long)z * sC + (long)(m0 + rr) * N + n0 + c4) = vv;
        } else {
            float v[4] = {vv.x, vv.y, vv.z, vv.w};
            if (bias) {
                float4 bb = *(const float4*)(bias + n0 + c4);
                v[0] += bb.x; v[1] += bb.y; v[2] += bb.z; v[3] += bb.w;
            }
            store_hl4(outH, outL, (long)z * sC + (long)(m0 + rr) * N + n0 + c4, v);
        }
    }
}

// --------------------------- flash attention (R14) ---------------------------
#define QPITCH 144
#define VPITCH 272
#define QS_OFF 0
#define QSB 18432
#define KS_OFF (2*QSB)
#define KSTG (2*QSB)
#define VS_OFF (KS_OFF + 2*KSTG)
#define VSB 17408
#define VSTG (2*VSB)
#define FSMEM (VS_OFF + 2*VSTG)    // 180224

__global__ void __launch_bounds__(256, 1) flash_kernel(
    const bf16* __restrict__ qh, const bf16* __restrict__ ql,
    const bf16* __restrict__ kh, const bf16* __restrict__ kl,
    const bf16* __restrict__ vth, const bf16* __restrict__ vtl,
    const float* __restrict__ amask,
    bf16* __restrict__ ch, bf16* __restrict__ cl)
{
    uint32_t su = smem_u32(smem_);
    int tid = threadIdx.x, w = tid >> 5, lane = tid & 31;
    int z = blockIdx.y;
    int b = z / HH, h = z - b * HH;
    int q0 = blockIdx.x * 128;
    const bf16* Qh = qh + (long)z * SS * DKK;
    const bf16* Ql = ql + (long)z * SS * DKK;
    const bf16* Kh = kh + (long)z * SS * DKK;
    const bf16* Kl = kl + (long)z * SS * DKK;
    const bf16* Vh = vth + (long)z * DKK * SS;
    const bf16* Vl = vtl + (long)z * DKK * SS;

    for (int i = tid; i < 1024; i += 256) {
        int r = i >> 3, c = i & 7;
        uint32_t so = su + QS_OFF + r * QPITCH + c * 16;
        long go = (long)(q0 + r) * DKK + c * 8;
        cpasync16(so,        Qh + go);
        cpasync16(so + QSB,  Ql + go);
    }
    auto loadKV = [&](int kt, int s) {
        for (int i = tid; i < 1024; i += 256) {
            int r = i >> 3, c = i & 7;
            uint32_t so = su + KS_OFF + s * KSTG + r * QPITCH + c * 16;
            long go = (long)(kt * 128 + r) * DKK + c * 8;
            cpasync16(so,        Kh + go);
            cpasync16(so + QSB,  Kl + go);
        }
        for (int i = tid; i < 1024; i += 256) {
            int r = i >> 4, c = i & 15;
            uint32_t so = su + VS_OFF + s * VSTG + r * VPITCH + c * 16;
            long go = (long)r * SS + kt * 128 + c * 8;
            cpasync16(so,        Vh + go);
            cpasync16(so + VSB,  Vl + go);
        }
        asm volatile("cp.async.commit_group;" ::: "memory");
    };
    loadKV(0, 0);

    float acc_o[8][4];
    #pragma unroll
    for (int j = 0; j < 8; j++)
        #pragma unroll
        for (int q = 0; q < 4; q++) acc_o[j][q] = 0.f;
    float rm[2] = {-INFINITY, -INFINITY};
    float rl[2] = {0.f, 0.f};
    int gr = lane >> 2, gc2 = (lane & 3) * 2;

    for (int kt = 0; kt < 4; kt++) {
        int s = kt & 1;
        asm volatile("cp.async.wait_group 0;" ::: "memory");
        __syncthreads();
        if (kt + 1 < 4) loadKV(kt + 1, s ^ 1);

        float accs[16][4];
        #pragma unroll
        for (int j = 0; j < 16; j++)
            #pragma unroll
            for (int q = 0; q < 4; q++) accs[j][q] = 0.f;
        uint32_t kbase = su + KS_OFF + s * KSTG;
        #pragma unroll
        for (int kb = 0; kb < 4; kb++) {
            uint32_t aqh[4], aql[4];
            uint32_t ad = su + QS_OFF + (w * 16 + (lane & 15)) * QPITCH
                          + kb * 32 + ((lane >> 4) * 16);
            ldmx4(aqh, ad);
            ldmx4(aql, ad + QSB);
            uint32_t bhf[2][4], blf[2][4];
            uint32_t bd0 = kbase + ((lane >> 4) * 8 + (lane & 7)) * QPITCH
                           + kb * 32 + (((lane >> 3) & 1) * 16);
            ldmx4(bhf[0], bd0);
            ldmx4(blf[0], bd0 + QSB);
            #pragma unroll
            for (int pr = 0; pr < 8; pr++) {
                int cur = pr & 1;
                if (pr < 7) {
                    uint32_t bd = bd0 + (pr + 1) * 16 * QPITCH;
                    ldmx4(bhf[cur ^ 1], bd);
                    ldmx4(blf[cur ^ 1], bd + QSB);
                }
                #pragma unroll
                for (int hf = 0; hf < 2; hf++)
                    mma16816(accs[pr * 2 + hf], aqh, bhf[cur][hf * 2], bhf[cur][hf * 2 + 1]);
                #pragma unroll
                for (int hf = 0; hf < 2; hf++)
                    mma16816(accs[pr * 2 + hf], aqh, blf[cur][hf * 2], blf[cur][hf * 2 + 1]);
                #pragma unroll
                for (int hf = 0; hf < 2; hf++)
                    mma16816(accs[pr * 2 + hf], aql, bhf[cur][hf * 2], bhf[cur][hf * 2 + 1]);
            }
        }

        const float* mrow = amask + b * SS + kt * 128;
        float tmax0 = -INFINITY, tmax1 = -INFINITY;
        #pragma unroll
        for (int nt = 0; nt < 16; nt++) {
            int c0 = nt * 8 + gc2;
            float m0 = mrow[c0], m1 = mrow[c0 + 1];
            float v0 = accs[nt][0] * SCALE, v1 = accs[nt][1] * SCALE;
            float v2 = accs[nt][2] * SCALE, v3 = accs[nt][3] * SCALE;
            if (m0 == 0.f) { v0 = -1e9f; v2 = -1e9f; }
            if (m1 == 0.f) { v1 = -1e9f; v3 = -1e9f; }
            accs[nt][0] = v0; accs[nt][1] = v1; accs[nt][2] = v2; accs[nt][3] = v3;
            tmax0 = fmaxf(tmax0, fmaxf(v0, v1));
            tmax1 = fmaxf(tmax1, fmaxf(v2, v3));
        }
        tmax0 = fmaxf(tmax0, __shfl_xor_sync(0xffffffffu, tmax0, 1));
        tmax0 = fmaxf(tmax0, __shfl_xor_sync(0xffffffffu, tmax0, 2));
        tmax1 = fmaxf(tmax1, __shfl_xor_sync(0xffffffffu, tmax1, 1));
        tmax1 = fmaxf(tmax1, __shfl_xor_sync(0xffffffffu, tmax1, 2));
        float nm0 = fmaxf(rm[0], tmax0), nm1 = fmaxf(rm[1], tmax1);
        float al0 = __expf(rm[0] - nm0), al1 = __expf(rm[1] - nm1);
        rm[0] = nm0; rm[1] = nm1;
        #pragma unroll
        for (int j = 0; j < 8; j++) {
            acc_o[j][0] *= al0; acc_o[j][1] *= al0;
            acc_o[j][2] *= al1; acc_o[j][3] *= al1;
        }
        rl[0] *= al0; rl[1] *= al1;

        uint32_t vbase = su + VS_OFF + s * VSTG;
        float rs0 = 0.f, rs1 = 0.f;
        #pragma unroll
        for (int kc = 0; kc < 8; kc++) {
            float p[2][4];
            #pragma unroll
            for (int hf = 0; hf < 2; hf++) {
                int nt = kc * 2 + hf;
                p[hf][0] = __expf(accs[nt][0] - nm0);
                p[hf][1] = __expf(accs[nt][1] - nm0);
                p[hf][2] = __expf(accs[nt][2] - nm1);
                p[hf][3] = __expf(accs[nt][3] - nm1);
                rs0 += p[hf][0] + p[hf][1];
                rs1 += p[hf][2] + p[hf][3];
            }
            uint32_t pah[4], pal[4];
            #pragma unroll
            for (int hf = 0; hf < 2; hf++) {
                float h0 = __bfloat162float(__float2bfloat16_rn(p[hf][0]));
                float h1 = __bfloat162float(__float2bfloat16_rn(p[hf][1]));
                float h2 = __bfloat162float(__float2bfloat16_rn(p[hf][2]));
                float h3 = __bfloat162float(__float2bfloat16_rn(p[hf][3]));
                pah[hf * 2]     = packbf2(h0, h1);
                pah[hf * 2 + 1] = packbf2(h2, h3);
                pal[hf * 2]     = packbf2(p[hf][0] - h0, p[hf][1] - h1);
                pal[hf * 2 + 1] = packbf2(p[hf][2] - h2, p[hf][3] - h3);
            }
            uint32_t vhf[2][4], vlf[2][4];
            uint32_t vd0 = vbase + ((lane >> 4) * 8 + (lane & 7)) * VPITCH
                           + kc * 32 + (((lane >> 3) & 1) * 16);
            ldmx4(vhf[0], vd0);
            ldmx4(vlf[0], vd0 + VSB);
            #pragma unroll
            for (int vp = 0; vp < 4; vp++) {
                int cur = vp & 1;
                if (vp < 3) {
                    uint32_t vd = vd0 + (vp + 1) * 16 * VPITCH;
                    ldmx4(vhf[cur ^ 1], vd);
                    ldmx4(vlf[cur ^ 1], vd + VSB);
                }
                #pragma unroll
                for (int hf = 0; hf < 2; hf++)
                    mma16816(acc_o[vp * 2 + hf], pah, vhf[cur][hf * 2], vhf[cur][hf * 2 + 1]);
                #pragma unroll
                for (int hf = 0; hf < 2; hf++)
                    mma16816(acc_o[vp * 2 + hf], pah, vlf[cur][hf * 2], vlf[cur][hf * 2 + 1]);
                #pragma unroll
                for (int hf = 0; hf < 2; hf++)
                    mma16816(acc_o[vp * 2 + hf], pal, vhf[cur][hf * 2], vhf[cur][hf * 2 + 1]);
            }
        }
        rl[0] += rs0;
        rl[1] += rs1;
    }
    rl[0] += __shfl_xor_sync(0xffffffffu, rl[0], 1);
    rl[0] += __shfl_xor_sync(0xffffffffu, rl[0], 2);
    rl[1] += __shfl_xor_sync(0xffffffffu, rl[1], 1);
    rl[1] += __shfl_xor_sync(0xffffffffu, rl[1], 2);
    __syncthreads();

    float* Cs = (float*)(smem_ + KS_OFF);     // [128][68]
    {
        float inv0 = 1.f / rl[0], inv1 = 1.f / rl[1];
        int r0 = w * 16 + gr;
        #pragma unroll
        for (int no = 0; no < 8; no++) {
            int col = no * 8 + gc2;
            Cs[r0 * 68 + col]           = acc_o[no][0] * inv0;
            Cs[r0 * 68 + col + 1]       = acc_o[no][1] * inv0;
            Cs[(r0 + 8) * 68 + col]     = acc_o[no][2] * inv1;
            Cs[(r0 + 8) * 68 + col + 1] = acc_o[no][3] * inv1;
        }
    }
    __syncthreads();
    for (int idx = tid; idx < 128 * 16; idx += 256) {
        int r = idx >> 4, c4 = (idx & 15) << 2;
        float4 vv = *(const float4*)(Cs + r * 68 + c4);
        float v[4] = {vv.x, vv.y, vv.z, vv.w};
        long dst = ((long)(b * SS + q0 + r)) * DD + h * DKK + c4;
        store_hl4(ch, cl, dst, v);
    }
}

// --------------------------- elementwise kernels -----------------------------
__device__ __forceinline__ float bsum(float v, float* sh) {
    int lane = threadIdx.x & 31, w = threadIdx.x >> 5;
    #pragma unroll
    for (int o = 16; o > 0; o >>= 1) v += __shfl_xor_sync(0xffffffffu, v, o);
    if (lane == 0) sh[w] = v;
    __syncthreads();
    float r = 0.f;
    #pragma unroll
    for (int i = 0; i < 8; i++) r += sh[i];
    __syncthreads();
    return r;
}
__device__ __forceinline__ void wsplit(bf16* H, bf16* L, long i, float v) {
    bf16 h = __float2bfloat16_rn(v);
    H[i] = h;
    L[i] = __float2bfloat16_rn(v - __bfloat162float(h));
}

#define S1 ((long)LL*DD*DD)
#define S2 ((long)LL*FF*DD)
__global__ void cvt_all_kernel(const float* __restrict__ Wq, const float* __restrict__ Wk,
                               const float* __restrict__ Wv, const float* __restrict__ Wo,
                               const float* __restrict__ W2,
                               bf16* __restrict__ qkvh, bf16* __restrict__ qkvl,
                               bf16* __restrict__ woh, bf16* __restrict__ wol,
                               bf16* __restrict__ w2h, bf16* __restrict__ w2l) {
    const long total = 4 * S1 + S2;
    long i = (long)blockIdx.x * 256 + threadIdx.x;
    long stride = (long)gridDim.x * 256;
    for (; i < total; i += stride) {
        long j = i;
        if (j < 3 * S1) {
            int seg = (int)(j / S1);
            long r = j - (long)seg * S1;
            const float* src = (seg == 0) ? Wq : (seg == 1) ? Wk : Wv;
            long l = r / (DD * DD);
            long rem = r - l * (DD * DD);
            long n = rem / DD, k = rem - n * DD;
            long dst = (l * NQKV + seg * DD + n) * DD + k;
            wsplit(qkvh, qkvl, dst, src[r]);
        } else if (j < 4 * S1) {
            long r = j - 3 * S1;
            wsplit(woh, wol, r, Wo[r]);
        } else {
            long r = j - 4 * S1;
            wsplit(w2h, w2l, r, W2[r]);
        }
    }
}

__global__ void cvt_w1t_kernel(const float* __restrict__ W1,
                               bf16* __restrict__ th, bf16* __restrict__ tl) {
    __shared__ float s[32][33];
    int l = blockIdx.z;
    int e0 = blockIdx.x * 32, f0 = blockIdx.y * 32;
    int tx = threadIdx.x, ty = threadIdx.y;     // (32, 8)
    const float* src = W1 + (long)l * FF * DD;
    #pragma unroll
    for (int i = 0; i < 4; i++)
        s[ty + i * 8][tx] = src[(long)(f0 + ty + i * 8) * DD + e0 + tx];
    __syncthreads();
    bf16* dh = th + (long)l * DD * FF;
    bf16* dl = tl + (long)l * DD * FF;
    #pragma unroll
    for (int i = 0; i < 4; i++) {
        float v = s[tx][ty + i * 8];
        long o = (long)(e0 + ty + i * 8) * FF + f0 + tx;
        wsplit(dh, dl, o, v);
    }
}

__global__ void beff_kernel(const float* __restrict__ W2, const float* __restrict__ b1,
                            const float* __restrict__ b2, float* __restrict__ beff) {
    __shared__ float sh[8];
    int ld = blockIdx.x;
    int l = ld / DD;
    const float* w = W2 + (long)ld * FF;
    const float* bb = b1 + (long)l * FF;
    float s = 0.f;
    for (int f = threadIdx.x; f < FF; f += 256) s += w[f] * bb[f];
    s = bsum(s, sh);
    if (threadIdx.x == 0) beff[ld] = s + b2[ld];
}

__global__ void embed_ln_kernel(const int* __restrict__ ids, const int* __restrict__ tt,
                                const float* __restrict__ we, const float* __restrict__ pe,
                                const float* __restrict__ te, const float* __restrict__ gamma,
                                const float* __restrict__ beta, float* __restrict__ outF,
                                bf16* __restrict__ outH, bf16* __restrict__ outL) {
    __shared__ float sh[8];
    int m = blockIdx.x, s = m & (SS - 1);
    int id = ids[m], ty = tt[m], t = threadIdx.x;
    float v[3];
    #pragma unroll
    for (int i = 0; i < 3; i++) {
        int d = t + i * 256;
        v[i] = we[(long)id * DD + d] + te[(long)ty * DD + d] + pe[(long)s * DD + d];
    }
    float mu = bsum(v[0] + v[1] + v[2], sh) * (1.f / DD);
    float qs = 0.f;
    #pragma unroll
    for (int i = 0; i < 3; i++) { float d0 = v[i] - mu; qs += d0 * d0; }
    float rstd = rsqrtf(bsum(qs, sh) * (1.f / DD) + 1e-12f);
    #pragma unroll
    for (int i = 0; i < 3; i++) {
        int d = t + i * 256;
        float y = (v[i] - mu) * rstd * gamma[d] + beta[d];
        outF[(long)m * DD + d] = y;
        wsplit(outH, outL, (long)m * DD + d, y);
    }
}

__global__ void ln768_kernel(const float* __restrict__ in, const float* __restrict__ resid,
                             const float* __restrict__ bias, const float* __restrict__ gamma,
                             const float* __restrict__ beta, float* __restrict__ outF,
                             bf16* __restrict__ outH, bf16* __restrict__ outL, float eps) {
    __shared__ float sh[8];
    long m = blockIdx.x;
    int t = threadIdx.x;
    float v[3];
    #pragma unroll
    for (int i = 0; i < 3; i++) {
        int d = t + i * 256;
        float x = in[m * DD + d];
        if (bias) x += bias[d];
        if (resid) x += resid[m * DD + d];
        v[i] = x;
    }
    float mu = bsum(v[0] + v[1] + v[2], sh) * (1.f / DD);
    float qs = 0.f;
    #pragma unroll
    for (int i = 0; i < 3; i++) { float d0 = v[i] - mu; qs += d0 * d0; }
    float rstd = rsqrtf(bsum(qs, sh) * (1.f / DD) + eps);
    #pragma unroll
    for (int i = 0; i < 3; i++) {
        int d = t + i * 256;
        float y = (v[i] - mu) * rstd * gamma[d] + beta[d];
        if (outF) outF[m * DD + d] = y;
        wsplit(outH, outL, m * DD + d, y);
    }
}

// ------------------------------- launch --------------------------------------
extern "C" void kernel_launch(void* const* d_in, const int* in_sizes, int n_in,
                              void* d_out, int out_size) {
    const int*   input_ids = (const int*)  d_in[0];
    const int*   type_ids  = (const int*)  d_in[1];
    const float* amask     = (const float*)d_in[2];
    const float* word_emb  = (const float*)d_in[3];
    const float* pos_emb   = (const float*)d_in[4];
    const float* type_emb  = (const float*)d_in[5];
    const float* emb_g     = (const float*)d_in[6];
    const float* emb_b     = (const float*)d_in[7];
    const float* Wq = (const float*)d_in[8];  const float* bq = (const float*)d_in[9];
    const float* Wk = (const float*)d_in[10]; const float* bk = (const float*)d_in[11];
    const float* Wv = (const float*)d_in[12]; const float* bv = (const float*)d_in[13];
    const float* Wo = (const float*)d_in[14]; const float* bo = (const float*)d_in[15];
    const float* ag = (const float*)d_in[16]; const float* ab = (const float*)d_in[17];
    const float* W1 = (const float*)d_in[18]; const float* b1 = (const float*)d_in[19];
    const float* W2 = (const float*)d_in[20]; const float* b2 = (const float*)d_in[21];
    const float* fg = (const float*)d_in[22]; const float* fb = (const float*)d_in[23];

    static int smem_set = 0;
    if (!smem_set) {
        cudaFuncSetAttribute(mm_kernel, cudaFuncAttributeMaxDynamicSharedMemorySize, MMSMEM);
        cudaFuncSetAttribute(mm64m_kernel, cudaFuncAttributeMaxDynamicSharedMemorySize, MM64MSMEM);
        cudaFuncSetAttribute(flash_kernel, cudaFuncAttributeMaxDynamicSharedMemorySize, FSMEM);
        smem_set = 1;
    }

    float *x, *t, *beff;
    bf16 *xh, *xl, *ah, *al, *qh, *ql, *kh, *kl, *vth, *vtl, *ch, *cl;
    bf16 *qkvh, *qkvl, *woh, *wol, *w1th, *w1tl, *w2h, *w2l, *weffh, *weffl;
    cudaGetSymbolAddress((void**)&x, g_x);     cudaGetSymbolAddress((void**)&t, g_t);
    cudaGetSymbolAddress((void**)&beff, g_beff);
    cudaGetSymbolAddress((void**)&xh, g_xh);   cudaGetSymbolAddress((void**)&xl, g_xl);
    cudaGetSymbolAddress((void**)&ah, g_ah);   cudaGetSymbolAddress((void**)&al, g_al);
    cudaGetSymbolAddress((void**)&qh, g_qh);   cudaGetSymbolAddress((void**)&ql, g_ql);
    cudaGetSymbolAddress((void**)&kh, g_kh);   cudaGetSymbolAddress((void**)&kl, g_kl);
    cudaGetSymbolAddress((void**)&vth, g_vth); cudaGetSymbolAddress((void**)&vtl, g_vtl);
    cudaGetSymbolAddress((void**)&ch, g_ch);   cudaGetSymbolAddress((void**)&cl, g_cl);
    cudaGetSymbolAddress((void**)&qkvh, g_wqkvh); cudaGetSymbolAddress((void**)&qkvl, g_wqkvl);
    cudaGetSymbolAddress((void**)&woh, g_woh); cudaGetSymbolAddress((void**)&wol, g_wol);
    cudaGetSymbolAddress((void**)&w1th, g_w1th); cudaGetSymbolAddress((void**)&w1tl, g_w1tl);
    cudaGetSymbolAddress((void**)&w2h, g_w2h); cudaGetSymbolAddress((void**)&w2l, g_w2l);
    cudaGetSymbolAddress((void**)&weffh, g_weffh); cudaGetSymbolAddress((void**)&weffl, g_weffl);

    cvt_all_kernel<<<8192, 256>>>(Wq, Wk, Wv, Wo, W2,
                                  qkvh, qkvl, woh, wol, w2h, w2l);
    cvt_w1t_kernel<<<dim3(DD / 32, FF / 32, LL), dim3(32, 8)>>>(W1, w1th, w1tl);
    beff_kernel<<<LL * DD, 256>>>(W2, b1, b2, beff);

    // Weff = W2 @ W1 all layers, BM=64 for wave packing: 864 CTAs
    mm64m_kernel<<<dim3(6, 12, LL), 128, MM64MSMEM>>>(w2h, w2l, (long)DD * FF,
        w1th, w1tl, (long)DD * FF, nullptr, DD, DD, FF,
        nullptr, weffh, weffl, (long)DD * DD, 1);

    embed_ln_kernel<<<MTOK, 256>>>(input_ids, type_ids, word_emb, pos_emb,
                                   type_emb, emb_g, emb_b, x, xh, xl);

    for (int l = 0; l < LL; l++) {
        const bf16* qkh = qkvh + (long)l * NQKV * DD;
        const bf16* qkl = qkvl + (long)l * NQKV * DD;
        // fused QKV
        mm_kernel<<<dim3(18, 32), 128, MMSMEM>>>(xh, xl, 0, qkh, qkl, 0,
            bq + l * DD, bk + l * DD, bv + l * DD, 1.f, MTOK, NQKV, DD,
            nullptr, qh, ql, kh, kl, vth, vtl, 0, 5);
        // fused attention
        flash_kernel<<<dim3(4, NHB), 256, FSMEM>>>(qh, ql, kh, kl, vth, vtl,
                                                   amask, ch, cl);
        // O projection -> fp32 t
        mm64m_kernel<<<dim3(6, 64), 128, MM64MSMEM>>>(ch, cl, 0,
            woh + (long)l * DD * DD, wol + (long)l * DD * DD, 0, nullptr,
            MTOK, DD, DD, t, nullptr, nullptr, 0, 0);
        ln768_kernel<<<MTOK, 256>>>(t, x, bo + l * DD, ag + l * DD, ab + l * DD,
                                    nullptr, ah, al, 1e-5f);
        // FFN collapsed: y = a @ Weff^T -> fp32 t
        mm64m_kernel<<<dim3(6, 64), 128, MM64MSMEM>>>(ah, al, 0,
            weffh + (long)l * DD * DD, weffl + (long)l * DD * DD, 0, nullptr,
            MTOK, DD, DD, t, nullptr, nullptr, 0, 0);
        ln768_kernel<<<MTOK, 256>>>(t, nullptr, beff + l * DD, fg + l * DD,
                                    fb + l * DD, x, xh, xl, 1e-5f);
    }

    cudaMemcpyAsync(d_out, x, (size_t)MTOK * DD * sizeof(float),
                    cudaMemcpyDeviceToDevice);
}